// round 11
// baseline (speedup 1.0000x reference)
#include <cuda_runtime.h>
#include <math.h>

// ---------------- problem constants ----------------
#define K_EMB   8192
#define D_EMB   256
#define N_TOK   16384          // 16 * 32 * 32
#define HW      1024           // 32*32
#define BATCH   16
#define QST_N   4194304        // 16*256*32*32

// output layout (concatenated float32, reference tuple order)
#define OFF_LOSS  0LL
#define OFF_QST   1LL
#define OFF_PERP  4194305LL
#define OFF_EMBO  4194306LL
#define OFF_CS    6291458LL
#define OFF_EMAW  6299650LL
#define OFF_IDX   8396802LL

// ---------------- scratch (static device memory; no allocations) ----------------
__device__ float g_counts[K_EMB];
__device__ float g_dw[K_EMB * D_EMB];
__device__ float g_esq[K_EMB];
__device__ float g_cs_pre[K_EMB];
__device__ int   g_idx[N_TOK];
__device__ float g_scal[3];   // [0]=loss sum, [1]=ntot, [2]=sum p*log(p)

typedef unsigned long long ull;

// packed fp32x2 FMA (Blackwell FFMA2)
__device__ __forceinline__ void ffma2(ull& acc, ull a, ull b) {
    asm("fma.rn.f32x2 %0, %1, %2, %0;" : "+l"(acc) : "l"(a), "l"(b));
}
// build (v, v) packed pair
__device__ __forceinline__ ull dup2(float v) {
    ull r; unsigned u = __float_as_uint(v);
    asm("mov.b64 %0, {%1, %2};" : "=l"(r) : "r"(u), "r"(u));
    return r;
}

// ---------------- kernel 0: zero scratch ----------------
__global__ void vq_zero_kernel() {
    int gi = blockIdx.x * blockDim.x + threadIdx.x;   // grid covers 2097152 exactly
    g_dw[gi] = 0.0f;
    if (gi < K_EMB) g_counts[gi] = 0.0f;
    if (gi < 3)     g_scal[gi]   = 0.0f;
}

// ---------------- kernel 1: ||e_k||^2 ----------------
__global__ void vq_esq_kernel(const float* __restrict__ emb) {
    int gi   = blockIdx.x * blockDim.x + threadIdx.x;
    int k    = gi >> 5;
    int lane = gi & 31;
    const float4* p = reinterpret_cast<const float4*>(emb + (size_t)k * D_EMB + lane * 8);
    float4 a = p[0], b = p[1];
    float s = a.x*a.x + a.y*a.y + a.z*a.z + a.w*a.w
            + b.x*b.x + b.y*b.y + b.z*b.z + b.w*b.w;
    #pragma unroll
    for (int o = 16; o > 0; o >>= 1) s += __shfl_down_sync(0xffffffffu, s, o);
    if (lane == 0) g_esq[k] = s;
}

// ---------------- kernel 2: fused distance GEMM + argmin ----------------
// CTA: 128 tokens x all 8192 codes. A tile resident in smem ([256 d][128 m]).
// Thread tile: 16 tokens (8 natural M-pairs) x 4 codes.
// Accumulators are M-paired ulls; A pairs load as aligned 64-bit from smem
// (conflict-free broadcast); B is plain float, one coalesced LDS.128 per
// thread per d-step (conflict-free), duplicated into (b,b) pairs in regs.
// B streamed double-buffered in 16-d chunks (compute per chunk > L2 latency).
__global__ void __launch_bounds__(256, 1)
vq_argmin_kernel(const float* __restrict__ x, const float* __restrict__ emb,
                 float* __restrict__ idx_f_out)
{
    extern __shared__ float smem[];
    float* As   = smem;                       // [256][128]         131072 B
    float* Bs   = smem + 32768;               // [2][16][128]        16384 B
    float* redv = smem + 32768 + 4096;        // [128][32]           16384 B
    int*   redi = reinterpret_cast<int*>(smem + 32768 + 4096 + 4096); // 16384 B

    const int tid = threadIdx.x;
    const int tn  = tid & 31;     // 4 codes: tn*4 .. tn*4+3
    const int tm  = tid >> 5;     // 16 tokens: tm*16 .. tm*16+15
    const int m0  = blockIdx.x << 7;
    const int b   = m0 >> 10;
    const float* xb = x + (size_t)b * (D_EMB * HW) + (m0 & 1023);

    // load A tile: As[d][m] = x[b][d][hw0+m]  (fully coalesced)
    #pragma unroll 4
    for (int i = tid; i < 256 * 32; i += 256) {
        int d = i >> 5, mq = i & 31;
        *reinterpret_cast<float4*>(&As[d * 128 + mq * 4]) =
            *reinterpret_cast<const float4*>(xb + (size_t)d * HW + mq * 4);
    }

    float bv[16]; int bi[16];
    #pragma unroll
    for (int i = 0; i < 16; i++) { bv[i] = 3.4e38f; bi[i] = 0; }

    // B producer mapping: thread (c, h) loads 8 d-values of code row c per chunk
    const int c = tid >> 1;       // code row within 128-tile
    const int h = tid & 1;        // which 8-d half of the 16-d chunk

    for (int nt = 0; nt < 64; ++nt) {
        const int k0 = nt << 7;
        const float* eb = emb + (((size_t)(k0 + c)) << 8) + (h << 3);

        ull acc[8][4];
        #pragma unroll
        for (int i = 0; i < 8; i++)
            #pragma unroll
            for (int j = 0; j < 4; j++) acc[i][j] = 0ULL;

        // prefetch chunk 0 into buffer 0
        {
            float4 p0 = *reinterpret_cast<const float4*>(eb);
            float4 p1 = *reinterpret_cast<const float4*>(eb + 4);
            float v[8] = { p0.x, p0.y, p0.z, p0.w, p1.x, p1.y, p1.z, p1.w };
            #pragma unroll
            for (int j = 0; j < 8; j++) Bs[((h << 3) + j) * 128 + c] = v[j];
        }
        __syncthreads();

        for (int ch = 0; ch < 16; ++ch) {
            float4 q0, q1;
            if (ch < 15) {
                q0 = *reinterpret_cast<const float4*>(eb + (ch + 1) * 16);
                q1 = *reinterpret_cast<const float4*>(eb + (ch + 1) * 16 + 4);
            }
            const int cur = ch & 1;
            const float* Bc = Bs + cur * 2048;
            #pragma unroll
            for (int dd = 0; dd < 16; ++dd) {
                const int drow = (ch << 4) + dd;
                // A: 8 natural M-pairs (broadcast within warp, conflict-free)
                const ulonglong2* ap =
                    reinterpret_cast<const ulonglong2*>(&As[drow * 128 + (tm << 4)]);
                ulonglong2 a01 = ap[0], a23 = ap[1], a45 = ap[2], a67 = ap[3];
                ull av[8] = { a01.x, a01.y, a23.x, a23.y, a45.x, a45.y, a67.x, a67.y };
                // B: 4 codes, one coalesced LDS.128 (lane*16B, conflict-free)
                float4 bb = *reinterpret_cast<const float4*>(&Bc[dd * 128 + (tn << 2)]);
                ull bd[4] = { dup2(bb.x), dup2(bb.y), dup2(bb.z), dup2(bb.w) };
                #pragma unroll
                for (int mp = 0; mp < 8; mp++)
                    #pragma unroll
                    for (int n = 0; n < 4; n++)
                        ffma2(acc[mp][n], av[mp], bd[n]);
            }
            if (ch < 15) {
                float* Bn = Bs + (cur ^ 1) * 2048;
                float v[8] = { q0.x, q0.y, q0.z, q0.w, q1.x, q1.y, q1.z, q1.w };
                #pragma unroll
                for (int j = 0; j < 8; j++) Bn[((h << 3) + j) * 128 + c] = v[j];
                __syncthreads();
            }
        }

        // epilogue: dist = ||e||^2 - 2*dot ; running argmin (codes ascending)
        float4 e = *reinterpret_cast<const float4*>(&g_esq[k0 + (tn << 2)]);
        float ev[4] = { e.x, e.y, e.z, e.w };
        #pragma unroll
        for (int mp = 0; mp < 8; mp++)
            #pragma unroll
            for (int n = 0; n < 4; n++) {
                ull a = acc[mp][n];
                float lo = __uint_as_float((unsigned)(a & 0xffffffffULL));
                float hi = __uint_as_float((unsigned)(a >> 32));
                float dl = ev[n] - 2.0f * lo;
                float dh = ev[n] - 2.0f * hi;
                int kk = k0 + (tn << 2) + n;
                if (dl < bv[2 * mp    ]) { bv[2 * mp    ] = dl; bi[2 * mp    ] = kk; }
                if (dh < bv[2 * mp + 1]) { bv[2 * mp + 1] = dh; bi[2 * mp + 1] = kk; }
            }
        // next nt writes buffer 0 while stragglers may still read buffer 1:
        // disjoint regions, and the post-store __syncthreads realigns everyone.
    }

    // cross-thread reduction over tn (32 candidates per token)
    __syncthreads();
    #pragma unroll
    for (int i = 0; i < 16; i++) {
        int m = (tm << 4) + i;
        redv[m * 32 + tn] = bv[i];
        redi[m * 32 + tn] = bi[i];
    }
    __syncthreads();
    if (tid < 128) {
        float best = redv[tid * 32];
        int   bidx = redi[tid * 32];
        #pragma unroll
        for (int t = 1; t < 32; t++) {
            float v  = redv[tid * 32 + t];
            int   ii = redi[tid * 32 + t];
            if (v < best || (v == best && ii < bidx)) { best = v; bidx = ii; }
        }
        g_idx[m0 + tid] = bidx;
        idx_f_out[m0 + tid] = (float)bidx;
    }
}

// ---------------- kernel 3: gather q_st, loss, counts, dw ----------------
__global__ void vq_quant_kernel(const float* __restrict__ x,
                                const float* __restrict__ emb,
                                float* __restrict__ outq)
{
    const int tx = threadIdx.x, ty = threadIdx.y;
    const int hw = blockIdx.x * 32 + tx;
    const int b  = blockIdx.y;
    const int n  = (b << 10) + hw;
    const int code = g_idx[n];
    const float* erow = emb + ((size_t)code << 8);
    float lsum = 0.0f;
    for (int d = ty; d < D_EMB; d += 8) {
        size_t xi = (((size_t)(b * D_EMB + d)) << 10) + hw;
        float xv = x[xi];
        float q  = __ldg(erow + d);
        outq[xi] = q;
        atomicAdd(&g_dw[(code << 8) + d], xv);
        float df = q - xv;
        lsum += df * df;
    }
    if (ty == 0) atomicAdd(&g_counts[code], 1.0f);

    __shared__ float s[256];
    int t = ty * 32 + tx;
    s[t] = lsum;
    __syncthreads();
    #pragma unroll
    for (int st = 128; st > 0; st >>= 1) {
        if (t < st) s[t] += s[t + st];
        __syncthreads();
    }
    if (t == 0) atomicAdd(&g_scal[0], s[0]);
}

// ---------------- kernel 4: EMA stage 1 (cs_pre, ntot, perplexity sum) --------
__global__ void vq_ema1_kernel(const float* __restrict__ ecs) {
    int k = blockIdx.x * 256 + threadIdx.x;   // grid 32 x 256 = 8192
    float cnt = g_counts[k];
    float pre = ecs[k] * 0.99f + 0.01f * cnt;
    g_cs_pre[k] = pre;
    float p  = cnt * (1.0f / 16384.0f);
    float pl = p * logf(p + 1e-10f);

    __shared__ float sp[256], sl[256];
    int t = threadIdx.x;
    sp[t] = pre; sl[t] = pl;
    __syncthreads();
    #pragma unroll
    for (int st = 128; st > 0; st >>= 1) {
        if (t < st) { sp[t] += sp[t + st]; sl[t] += sl[t + st]; }
        __syncthreads();
    }
    if (t == 0) { atomicAdd(&g_scal[1], sp[0]); atomicAdd(&g_scal[2], sl[0]); }
}

// ---------------- kernel 5: EMA stage 2 (finalize all outputs) ----------------
__global__ void vq_ema2_kernel(const float* __restrict__ emaw, float* __restrict__ out) {
    int k = blockIdx.x;          // 8192
    int d = threadIdx.x;         // 256
    float ntot = g_scal[1];
    float ncs  = (g_cs_pre[k] + 1e-5f) / (ntot + 8192.0f * 1e-5f) * ntot;
    int i = (k << 8) + d;
    float nw = emaw[i] * 0.99f + 0.01f * g_dw[i];
    out[OFF_EMBO + i] = nw / ncs;
    out[OFF_EMAW + i] = nw;
    if (d == 0) out[OFF_CS + k] = ncs;
    if (k == 0 && d == 0) {
        out[OFF_LOSS] = 0.25f * g_scal[0] * (1.0f / 4194304.0f);
        out[OFF_PERP] = expf(-g_scal[2]);
    }
}

// ---------------- launch ----------------
extern "C" void kernel_launch(void* const* d_in, const int* in_sizes, int n_in,
                              void* d_out, int out_size)
{
    const float* x = nullptr; const float* emb = nullptr;
    const float* ecs = nullptr; const float* emaw = nullptr;
    for (int i = 0; i < n_in; i++) {
        int s = in_sizes[i];
        if (s == QST_N) x = (const float*)d_in[i];
        else if (s == K_EMB) ecs = (const float*)d_in[i];
        else if (s == K_EMB * D_EMB) {
            if (!emb) emb = (const float*)d_in[i];
            else emaw = (const float*)d_in[i];
        }
    }
    if (!x)    x    = (const float*)d_in[0];
    if (!emb)  emb  = (const float*)d_in[1];
    if (!ecs)  ecs  = (const float*)d_in[2];
    if (!emaw) emaw = (const float*)d_in[3];
    float* out = (float*)d_out;

    static const size_t ARGMIN_SMEM = (32768 + 4096 + 4096 + 4096) * sizeof(float); // 180224 B
    cudaFuncSetAttribute(vq_argmin_kernel,
                         cudaFuncAttributeMaxDynamicSharedMemorySize,
                         (int)ARGMIN_SMEM);

    vq_zero_kernel<<<2048, 1024>>>();
    vq_esq_kernel<<<1024, 256>>>(emb);
    vq_argmin_kernel<<<128, 256, ARGMIN_SMEM>>>(x, emb, out + OFF_IDX);
    vq_quant_kernel<<<dim3(32, 16), dim3(32, 8)>>>(x, emb, out + OFF_QST);
    vq_ema1_kernel<<<32, 256>>>(ecs);
    vq_ema2_kernel<<<8192, 256>>>(emaw, out);
    (void)out_size;
}

// round 14
// speedup vs baseline: 1.1936x; 1.1936x over previous
#include <cuda_runtime.h>
#include <cuda_bf16.h>
#include <cstdint>
#include <math.h>

// ---------------- problem constants ----------------
#define K_EMB   8192
#define D_EMB   256
#define N_TOK   16384          // 16 * 32 * 32
#define HW      1024           // 32*32
#define BATCH   16
#define QST_N   4194304        // 16*256*32*32

// output layout (concatenated float32, reference tuple order)
#define OFF_LOSS  0LL
#define OFF_QST   1LL
#define OFF_PERP  4194305LL
#define OFF_EMBO  4194306LL
#define OFF_CS    6291458LL
#define OFF_EMAW  6299650LL
#define OFF_IDX   8396802LL

// ---------------- scratch (static device memory; no allocations) ----------------
__device__ float g_counts[K_EMB];
__device__ float g_dw[K_EMB * D_EMB];
__device__ float g_esq[K_EMB];
__device__ float g_cs_pre[K_EMB];
__device__ int   g_idx[N_TOK];
__device__ int   g_top1[N_TOK];
__device__ int   g_top2[N_TOK];
__device__ float g_scal[3];   // [0]=loss sum, [1]=ntot, [2]=sum p*log(p)

// bf16 split buffers
__device__ __nv_bfloat16 g_xh[N_TOK * D_EMB];   // [16384][256] token-major
__device__ __nv_bfloat16 g_xl[N_TOK * D_EMB];
__device__ __nv_bfloat16 g_eh[K_EMB * D_EMB];   // [8192][256]
__device__ __nv_bfloat16 g_el[K_EMB * D_EMB];

// ---------------- helpers ----------------
__device__ __forceinline__ uint32_t smem_u32(const void* p) {
    uint32_t a;
    asm("{ .reg .u64 t; cvta.to.shared.u64 t, %1; cvt.u32.u64 %0, t; }" : "=r"(a) : "l"(p));
    return a;
}
__device__ __forceinline__ void ldsm4(uint32_t r[4], uint32_t addr) {
    asm volatile("ldmatrix.sync.aligned.m8n8.x4.shared.b16 {%0,%1,%2,%3}, [%4];"
                 : "=r"(r[0]), "=r"(r[1]), "=r"(r[2]), "=r"(r[3]) : "r"(addr));
}
__device__ __forceinline__ void mma16816(float d[4], const uint32_t a[4],
                                         uint32_t b0, uint32_t b1) {
    asm volatile(
        "mma.sync.aligned.m16n8k16.row.col.f32.bf16.bf16.f32 "
        "{%0,%1,%2,%3}, {%4,%5,%6,%7}, {%8,%9}, {%0,%1,%2,%3};"
        : "+f"(d[0]), "+f"(d[1]), "+f"(d[2]), "+f"(d[3])
        : "r"(a[0]), "r"(a[1]), "r"(a[2]), "r"(a[3]), "r"(b0), "r"(b1));
}
#define CP_ASYNC16(dst, src) \
    asm volatile("cp.async.cg.shared.global [%0], [%1], 16;" :: "r"(dst), "l"(src) : "memory")
#define CP_COMMIT()  asm volatile("cp.async.commit_group;" ::: "memory")
#define CP_WAIT0()   asm volatile("cp.async.wait_group 0;" ::: "memory")

// ---------------- kernel 0: zero scratch ----------------
__global__ void vq_zero_kernel() {
    int gi = blockIdx.x * blockDim.x + threadIdx.x;   // covers 2097152
    g_dw[gi] = 0.0f;
    if (gi < K_EMB) g_counts[gi] = 0.0f;
    if (gi < 3)     g_scal[gi]   = 0.0f;
}

// ---------------- kernel 1: ||e_k||^2 ----------------
__global__ void vq_esq_kernel(const float* __restrict__ emb) {
    int gi   = blockIdx.x * blockDim.x + threadIdx.x;
    int k    = gi >> 5;
    int lane = gi & 31;
    const float4* p = reinterpret_cast<const float4*>(emb + (size_t)k * D_EMB + lane * 8);
    float4 a = p[0], b = p[1];
    float s = a.x*a.x + a.y*a.y + a.z*a.z + a.w*a.w
            + b.x*b.x + b.y*b.y + b.z*b.z + b.w*b.w;
    #pragma unroll
    for (int o = 16; o > 0; o >>= 1) s += __shfl_down_sync(0xffffffffu, s, o);
    if (lane == 0) g_esq[k] = s;
}

// ---------------- kernel 1b: split emb -> bf16 hi/lo ----------------
__global__ void vq_convemb_kernel(const float* __restrict__ emb) {
    int gi = blockIdx.x * 256 + threadIdx.x;          // 524288 threads x 4 elems
    float4 v = reinterpret_cast<const float4*>(emb)[gi];
    float f[4] = { v.x, v.y, v.z, v.w };
    __nv_bfloat16 h[4], l[4];
    #pragma unroll
    for (int i = 0; i < 4; i++) {
        h[i] = __float2bfloat16(f[i]);
        l[i] = __float2bfloat16(f[i] - __bfloat162float(h[i]));
    }
    __nv_bfloat162 hp0; hp0.x = h[0]; hp0.y = h[1];
    __nv_bfloat162 hp1; hp1.x = h[2]; hp1.y = h[3];
    __nv_bfloat162 lp0; lp0.x = l[0]; lp0.y = l[1];
    __nv_bfloat162 lp1; lp1.x = l[2]; lp1.y = l[3];
    reinterpret_cast<__nv_bfloat162*>(g_eh)[gi * 2    ] = hp0;
    reinterpret_cast<__nv_bfloat162*>(g_eh)[gi * 2 + 1] = hp1;
    reinterpret_cast<__nv_bfloat162*>(g_el)[gi * 2    ] = lp0;
    reinterpret_cast<__nv_bfloat162*>(g_el)[gi * 2 + 1] = lp1;
}

// ---------------- kernel 1c: transpose+split x -> xh/xl [token][d] ----------------
__global__ void vq_convx_kernel(const float* __restrict__ x) {
    __shared__ float t[64][33];
    int h0 = blockIdx.x * 32;
    int d0 = blockIdx.y * 64;
    int b  = blockIdx.z;
    int tx = threadIdx.x, ty = threadIdx.y;
    const float* xb = x + ((size_t)b * D_EMB + d0) * HW + h0;
    t[ty     ][tx] = xb[(size_t)ty * HW + tx];
    t[ty + 32][tx] = xb[(size_t)(ty + 32) * HW + tx];
    __syncthreads();
    float v0 = t[tx * 2][ty], v1 = t[tx * 2 + 1][ty];
    __nv_bfloat16 h0b = __float2bfloat16(v0);
    __nv_bfloat16 h1b = __float2bfloat16(v1);
    __nv_bfloat16 l0b = __float2bfloat16(v0 - __bfloat162float(h0b));
    __nv_bfloat16 l1b = __float2bfloat16(v1 - __bfloat162float(h1b));
    __nv_bfloat162 hp; hp.x = h0b; hp.y = h1b;
    __nv_bfloat162 lp; lp.x = l0b; lp.y = l1b;
    size_t o = ((size_t)(b * HW + h0 + ty)) * D_EMB + d0;
    reinterpret_cast<__nv_bfloat162*>(g_xh + o)[tx] = hp;
    reinterpret_cast<__nv_bfloat162*>(g_xl + o)[tx] = lp;
}

// ---------------- kernel 2: HMMA distance GEMM + approx top-2 ----------------
// 128 CTAs x 128 threads (4 warps). A (xh,xl; 128 tokens x 256 K) resident in
// XOR-swizzled smem; codes streamed 128n x 64k per chunk, double-buffered via
// cp.async. Warp tile 64m x 64n (bf16x3 -> one fp32 acc). Epilogue tracks the
// top-2 distances per slot; final reduction merges 8 slots -> (k1, k2) per
// token. Exact fp32 rescoring happens in vq_rescore_kernel.
#define SMA_TYPE 65536
#define SMB_OFF  131072
#define SMB_BUF  32768
#define SMB_TYPE 16384
#define SM_TOTAL2 196608

__global__ void __launch_bounds__(128, 1)
vq_argmin_mma_kernel()
{
    extern __shared__ char smem[];
    const uint32_t sbA = smem_u32(smem);
    const uint32_t sbB = sbA + SMB_OFF;
    const int tid  = threadIdx.x;
    const int lane = tid & 31;
    const int wid  = tid >> 5;
    const int wm   = wid >> 1;     // 0..1 -> m offset 64*wm
    const int wn   = wid & 1;      // 0..1 -> n offset 64*wn
    const int m0   = blockIdx.x << 7;

    // ---- resident A fill: [type][m][k] bf16, swizzled ----
    {
        const uint4* gsrc[2] = {
            reinterpret_cast<const uint4*>(g_xh) + (size_t)m0 * 32,
            reinterpret_cast<const uint4*>(g_xl) + (size_t)m0 * 32 };
        #pragma unroll
        for (int it = 0; it < 64; it++) {
            int i  = tid + it * 128;
            int ty = i >> 12;
            int j  = i & 4095;
            int m  = j >> 5;
            int s  = j & 31;
            uint4 v = gsrc[ty][m * 32 + s];
            uint32_t byte = (uint32_t)(m * 512 + s * 16);
            byte ^= (uint32_t)((m & 7) << 4);
            *reinterpret_cast<uint4*>(smem + ty * SMA_TYPE + byte) = v;
        }
    }

    auto issue_fill = [&](int t, int c, int buf) {
        const char* srcs[2] = { (const char*)g_eh, (const char*)g_el };
        const int k0t = t << 7;
        const uint32_t base = sbB + buf * SMB_BUF;
        #pragma unroll
        for (int it = 0; it < 16; it++) {
            int i  = tid + it * 128;
            int ty = i >> 10;
            int j  = i & 1023;
            int n  = j >> 3;
            int s  = j & 7;
            uint32_t byte = (uint32_t)(n * 128 + s * 16);
            uint32_t dst  = base + ty * SMB_TYPE + (byte ^ ((byte >> 3) & 0x70u));
            const char* src = srcs[ty] + ((size_t)(k0t + n) * 256 + c * 64 + s * 8) * 2;
            CP_ASYNC16(dst, src);
        }
    };

    issue_fill(0, 0, 0);
    CP_COMMIT();

    // lane-invariant ldmatrix addressing
    const int l7 = lane & 7, lt = lane >> 3;
    const int mlane = wm * 64 + ((lt & 1) << 3) + l7;   // + mf*16
    const int nlane = wn * 64 + ((lt & 1) << 3) + l7;   // + nq*16
    const int kloff = (lt >> 1) << 3;                   // 0 or 8
    const uint32_t aXor = (uint32_t)((mlane & 7) << 4);
    const uint32_t bXor = (uint32_t)((nlane & 7) << 4);

    float acc[4][8][4];
    #pragma unroll
    for (int a = 0; a < 4; a++)
        #pragma unroll
        for (int b = 0; b < 8; b++)
            #pragma unroll
            for (int c = 0; c < 4; c++) acc[a][b][c] = 0.0f;

    // top-2 per slot (slot = mf*2 + rowhalf)
    float v1[8], v2[8]; int i1[8], i2[8];
    #pragma unroll
    for (int i = 0; i < 8; i++) { v1[i] = 3.4e38f; v2[i] = 3.4e38f; i1[i] = 0; i2[i] = 0; }

    for (int t = 0; t < 64; ++t) {
        for (int c = 0; c < 4; ++c) {
            const int gc  = (t << 2) + c;
            const int buf = gc & 1;
            CP_WAIT0();
            __syncthreads();
            if (gc < 255) {
                int nt = gc + 1;
                issue_fill(nt >> 2, nt & 3, nt & 1);
            }
            CP_COMMIT();

            #pragma unroll
            for (int split = 0; split < 3; split++) {
                const uint32_t aBase = sbA + (split == 1 ? SMA_TYPE : 0);
                const uint32_t bBase = sbB + buf * SMB_BUF + (split == 2 ? SMB_TYPE : 0);
                #pragma unroll
                for (int ks = 0; ks < 4; ks++) {
                    const int kg = c * 64 + ks * 16;
                    const int kk = ks * 16;
                    const uint32_t akb = (uint32_t)((kg + kloff) * 2) ^ aXor;
                    const uint32_t bkb = (uint32_t)((kk + kloff) * 2) ^ bXor;
                    uint32_t af[4][4], bf[4][4];
                    #pragma unroll
                    for (int mf = 0; mf < 4; mf++)
                        ldsm4(af[mf], aBase + (uint32_t)((mlane + mf * 16) * 512) + akb);
                    #pragma unroll
                    for (int nq = 0; nq < 4; nq++)
                        ldsm4(bf[nq], bBase + (uint32_t)((nlane + nq * 16) * 128) + bkb);
                    #pragma unroll
                    for (int mf = 0; mf < 4; mf++)
                        #pragma unroll
                        for (int nq = 0; nq < 4; nq++) {
                            mma16816(acc[mf][2 * nq    ], af[mf], bf[nq][0], bf[nq][2]);
                            mma16816(acc[mf][2 * nq + 1], af[mf], bf[nq][1], bf[nq][3]);
                        }
                }
            }
        }

        // ---- per-tile epilogue: dist = ||e||^2 - 2*dot, fold top-2 ----
        const int nbase = (t << 7) + wn * 64 + (lane & 3) * 2;
        #pragma unroll
        for (int nf = 0; nf < 8; nf++) {
            const int n = nbase + nf * 8;
            float2 eq = *reinterpret_cast<const float2*>(g_esq + n);
            #pragma unroll
            for (int mf = 0; mf < 4; mf++) {
                float* a = acc[mf][nf];
                float d[4] = { eq.x - 2.0f * a[0], eq.y - 2.0f * a[1],
                               eq.x - 2.0f * a[2], eq.y - 2.0f * a[3] };
                int   ni[4] = { n, n + 1, n, n + 1 };
                #pragma unroll
                for (int q = 0; q < 4; q++) {
                    const int s = mf * 2 + (q >> 1);
                    float dv = d[q]; int nn = ni[q];
                    if (dv < v1[s]) {
                        v2[s] = v1[s]; i2[s] = i1[s];
                        v1[s] = dv;    i1[s] = nn;
                    } else if (dv < v2[s]) {
                        v2[s] = dv;    i2[s] = nn;
                    }
                }
                a[0] = 0.0f; a[1] = 0.0f; a[2] = 0.0f; a[3] = 0.0f;
            }
        }
    }

    // ---- final cross-thread top-2 merge (reuse A smem as scratch) ----
    __syncthreads();
    float* sv1 = reinterpret_cast<float*>(smem);            // [128][8]
    int*   si1 = reinterpret_cast<int*>(smem + 4096);
    float* sv2 = reinterpret_cast<float*>(smem + 8192);
    int*   si2 = reinterpret_cast<int*>(smem + 12288);
    const int slot = wn * 4 + (lane & 3);
    #pragma unroll
    for (int mf = 0; mf < 4; mf++)
        #pragma unroll
        for (int r = 0; r < 2; r++) {
            int m = wm * 64 + mf * 16 + r * 8 + (lane >> 2);
            int s = mf * 2 + r;
            sv1[m * 8 + slot] = v1[s]; si1[m * 8 + slot] = i1[s];
            sv2[m * 8 + slot] = v2[s]; si2[m * 8 + slot] = i2[s];
        }
    __syncthreads();
    {
        float V1 = 3.4e38f, V2 = 3.4e38f; int I1 = 0, I2 = 0;
        #pragma unroll
        for (int s = 0; s < 8; s++) {
            float a1 = sv1[tid * 8 + s]; int a1i = si1[tid * 8 + s];
            float a2 = sv2[tid * 8 + s]; int a2i = si2[tid * 8 + s];
            if (a1 < V1 || (a1 == V1 && a1i < I1)) {
                V2 = V1; I2 = I1; V1 = a1; I1 = a1i;
            } else if (a1 < V2) { V2 = a1; I2 = a1i; }
            if (a2 < V2) { V2 = a2; I2 = a2i; }
        }
        g_top1[m0 + tid] = I1;
        g_top2[m0 + tid] = I2;
    }
}

// ---------------- kernel 2b: exact fp32 rescore of top-2 ----------------
// block (32,8): 32 consecutive tokens (same batch), ty strides d.
__global__ void vq_rescore_kernel(const float* __restrict__ x,
                                  const float* __restrict__ emb,
                                  float* __restrict__ idx_f_out)
{
    const int tx = threadIdx.x, ty = threadIdx.y;
    const int n0 = blockIdx.x * 32;
    const int b  = n0 >> 10;
    const int hw = (n0 & 1023) + tx;
    const int n  = n0 + tx;
    const int k1 = g_top1[n], k2 = g_top2[n];
    const float* e1 = emb + ((size_t)k1 << 8);
    const float* e2 = emb + ((size_t)k2 << 8);
    float s1 = 0.0f, s2 = 0.0f;
    for (int d = ty; d < D_EMB; d += 8) {
        float xv = x[(((size_t)(b * D_EMB + d)) << 10) + hw];
        s1 += xv * __ldg(e1 + d);
        s2 += xv * __ldg(e2 + d);
    }
    __shared__ float sh1[8][32], sh2[8][32];
    sh1[ty][tx] = s1; sh2[ty][tx] = s2;
    __syncthreads();
    if (ty == 0) {
        float t1 = 0.0f, t2 = 0.0f;
        #pragma unroll
        for (int j = 0; j < 8; j++) { t1 += sh1[j][tx]; t2 += sh2[j][tx]; }
        float d1 = g_esq[k1] - 2.0f * t1;
        float d2 = g_esq[k2] - 2.0f * t2;
        int w = (d2 < d1 || (d2 == d1 && k2 < k1)) ? k2 : k1;
        g_idx[n] = w;
        idx_f_out[n] = (float)w;
    }
}

// ---------------- kernel 3: gather q_st, loss, counts, dw ----------------
__global__ void vq_quant_kernel(const float* __restrict__ x,
                                const float* __restrict__ emb,
                                float* __restrict__ outq)
{
    const int tx = threadIdx.x, ty = threadIdx.y;
    const int hw = blockIdx.x * 32 + tx;
    const int b  = blockIdx.y;
    const int n  = (b << 10) + hw;
    const int code = g_idx[n];
    const float* erow = emb + ((size_t)code << 8);
    float lsum = 0.0f;
    for (int d = ty; d < D_EMB; d += 8) {
        size_t xi = (((size_t)(b * D_EMB + d)) << 10) + hw;
        float xv = x[xi];
        float q  = __ldg(erow + d);
        outq[xi] = q;
        atomicAdd(&g_dw[(code << 8) + d], xv);
        float df = q - xv;
        lsum += df * df;
    }
    if (ty == 0) atomicAdd(&g_counts[code], 1.0f);

    __shared__ float s[256];
    int t = ty * 32 + tx;
    s[t] = lsum;
    __syncthreads();
    #pragma unroll
    for (int st = 128; st > 0; st >>= 1) {
        if (t < st) s[t] += s[t + st];
        __syncthreads();
    }
    if (t == 0) atomicAdd(&g_scal[0], s[0]);
}

// ---------------- kernel 4: EMA stage 1 ----------------
__global__ void vq_ema1_kernel(const float* __restrict__ ecs) {
    int k = blockIdx.x * 256 + threadIdx.x;
    float cnt = g_counts[k];
    float pre = ecs[k] * 0.99f + 0.01f * cnt;
    g_cs_pre[k] = pre;
    float p  = cnt * (1.0f / 16384.0f);
    float pl = p * logf(p + 1e-10f);

    __shared__ float sp[256], sl[256];
    int t = threadIdx.x;
    sp[t] = pre; sl[t] = pl;
    __syncthreads();
    #pragma unroll
    for (int st = 128; st > 0; st >>= 1) {
        if (t < st) { sp[t] += sp[t + st]; sl[t] += sl[t + st]; }
        __syncthreads();
    }
    if (t == 0) { atomicAdd(&g_scal[1], sp[0]); atomicAdd(&g_scal[2], sl[0]); }
}

// ---------------- kernel 5: EMA stage 2 ----------------
__global__ void vq_ema2_kernel(const float* __restrict__ emaw, float* __restrict__ out) {
    int k = blockIdx.x;
    int d = threadIdx.x;
    float ntot = g_scal[1];
    float ncs  = (g_cs_pre[k] + 1e-5f) / (ntot + 8192.0f * 1e-5f) * ntot;
    int i = (k << 8) + d;
    float nw = emaw[i] * 0.99f + 0.01f * g_dw[i];
    out[OFF_EMBO + i] = nw / ncs;
    out[OFF_EMAW + i] = nw;
    if (d == 0) out[OFF_CS + k] = ncs;
    if (k == 0 && d == 0) {
        out[OFF_LOSS] = 0.25f * g_scal[0] * (1.0f / 4194304.0f);
        out[OFF_PERP] = expf(-g_scal[2]);
    }
}

// ---------------- launch ----------------
extern "C" void kernel_launch(void* const* d_in, const int* in_sizes, int n_in,
                              void* d_out, int out_size)
{
    const float* x = nullptr; const float* emb = nullptr;
    const float* ecs = nullptr; const float* emaw = nullptr;
    for (int i = 0; i < n_in; i++) {
        int s = in_sizes[i];
        if (s == QST_N) x = (const float*)d_in[i];
        else if (s == K_EMB) ecs = (const float*)d_in[i];
        else if (s == K_EMB * D_EMB) {
            if (!emb) emb = (const float*)d_in[i];
            else emaw = (const float*)d_in[i];
        }
    }
    if (!x)    x    = (const float*)d_in[0];
    if (!emb)  emb  = (const float*)d_in[1];
    if (!ecs)  ecs  = (const float*)d_in[2];
    if (!emaw) emaw = (const float*)d_in[3];
    float* out = (float*)d_out;

    cudaFuncSetAttribute(vq_argmin_mma_kernel,
                         cudaFuncAttributeMaxDynamicSharedMemorySize, SM_TOTAL2);

    vq_zero_kernel<<<2048, 1024>>>();
    vq_convemb_kernel<<<2048, 256>>>(emb);
    vq_convx_kernel<<<dim3(32, 4, 16), dim3(32, 32)>>>(x);
    vq_esq_kernel<<<1024, 256>>>(emb);
    vq_argmin_mma_kernel<<<128, 128, SM_TOTAL2>>>();
    vq_rescore_kernel<<<512, dim3(32, 8)>>>(x, emb, out + OFF_IDX);
    vq_quant_kernel<<<dim3(32, 16), dim3(32, 8)>>>(x, emb, out + OFF_QST);
    vq_ema1_kernel<<<32, 256>>>(ecs);
    vq_ema2_kernel<<<8192, 256>>>(emaw, out);
    (void)out_size;
}

// round 15
// speedup vs baseline: 2.8028x; 2.3483x over previous
#include <cuda_runtime.h>
#include <cuda_bf16.h>
#include <cstdint>
#include <math.h>

// ---------------- problem constants ----------------
#define K_EMB   8192
#define D_EMB   256
#define N_TOK   16384          // 16 * 32 * 32
#define HW      1024           // 32*32
#define BATCH   16
#define QST_N   4194304        // 16*256*32*32

// output layout (concatenated float32, reference tuple order)
#define OFF_LOSS  0LL
#define OFF_QST   1LL
#define OFF_PERP  4194305LL
#define OFF_EMBO  4194306LL
#define OFF_CS    6291458LL
#define OFF_EMAW  6299650LL
#define OFF_IDX   8396802LL

// ---------------- scratch (static device memory; no allocations) ----------------
__device__ float g_counts[K_EMB];
__device__ float g_dw[K_EMB * D_EMB];
__device__ float g_esq[K_EMB];
__device__ float g_cs_pre[K_EMB];
__device__ int   g_idx[N_TOK];
__device__ int   g_cand[N_TOK * 8];     // top-8 approx candidates per token
__device__ float g_scal[3];   // [0]=loss sum, [1]=ntot, [2]=sum p*log(p)

// bf16 screen buffers (hi parts only — screen is approximate, rescore is exact)
__device__ __nv_bfloat16 g_xh[N_TOK * D_EMB];   // [16384][256] token-major
__device__ __nv_bfloat16 g_eh[K_EMB * D_EMB];   // [8192][256]

// ---------------- helpers ----------------
__device__ __forceinline__ uint32_t smem_u32(const void* p) {
    uint32_t a;
    asm("{ .reg .u64 t; cvta.to.shared.u64 t, %1; cvt.u32.u64 %0, t; }" : "=r"(a) : "l"(p));
    return a;
}
__device__ __forceinline__ void ldsm4(uint32_t r[4], uint32_t addr) {
    asm volatile("ldmatrix.sync.aligned.m8n8.x4.shared.b16 {%0,%1,%2,%3}, [%4];"
                 : "=r"(r[0]), "=r"(r[1]), "=r"(r[2]), "=r"(r[3]) : "r"(addr));
}
__device__ __forceinline__ void mma16816(float d[4], const uint32_t a[4],
                                         uint32_t b0, uint32_t b1) {
    asm volatile(
        "mma.sync.aligned.m16n8k16.row.col.f32.bf16.bf16.f32 "
        "{%0,%1,%2,%3}, {%4,%5,%6,%7}, {%8,%9}, {%0,%1,%2,%3};"
        : "+f"(d[0]), "+f"(d[1]), "+f"(d[2]), "+f"(d[3])
        : "r"(a[0]), "r"(a[1]), "r"(a[2]), "r"(a[3]), "r"(b0), "r"(b1));
}
#define CP_ASYNC16(dst, src) \
    asm volatile("cp.async.cg.shared.global [%0], [%1], 16;" :: "r"(dst), "l"(src) : "memory")
#define CP_COMMIT()      asm volatile("cp.async.commit_group;" ::: "memory")
#define CP_WAIT_GROUP2() asm volatile("cp.async.wait_group 2;" ::: "memory")
#define CP_WAIT_ALL()    asm volatile("cp.async.wait_group 0;" ::: "memory")

// ---------------- kernel 0: zero scratch ----------------
__global__ void vq_zero_kernel() {
    int gi = blockIdx.x * blockDim.x + threadIdx.x;   // covers 2097152
    g_dw[gi] = 0.0f;
    if (gi < K_EMB) g_counts[gi] = 0.0f;
    if (gi < 3)     g_scal[gi]   = 0.0f;
}

// ---------------- kernel 1: ||e_k||^2 ----------------
__global__ void vq_esq_kernel(const float* __restrict__ emb) {
    int gi   = blockIdx.x * blockDim.x + threadIdx.x;
    int k    = gi >> 5;
    int lane = gi & 31;
    const float4* p = reinterpret_cast<const float4*>(emb + (size_t)k * D_EMB + lane * 8);
    float4 a = p[0], b = p[1];
    float s = a.x*a.x + a.y*a.y + a.z*a.z + a.w*a.w
            + b.x*b.x + b.y*b.y + b.z*b.z + b.w*b.w;
    #pragma unroll
    for (int o = 16; o > 0; o >>= 1) s += __shfl_down_sync(0xffffffffu, s, o);
    if (lane == 0) g_esq[k] = s;
}

// ---------------- kernel 1b: emb -> bf16 ----------------
__global__ void vq_convemb_kernel(const float* __restrict__ emb) {
    int gi = blockIdx.x * 256 + threadIdx.x;          // 524288 threads x 4 elems
    float4 v = reinterpret_cast<const float4*>(emb)[gi];
    __nv_bfloat162 h0; h0.x = __float2bfloat16(v.x); h0.y = __float2bfloat16(v.y);
    __nv_bfloat162 h1; h1.x = __float2bfloat16(v.z); h1.y = __float2bfloat16(v.w);
    reinterpret_cast<__nv_bfloat162*>(g_eh)[gi * 2    ] = h0;
    reinterpret_cast<__nv_bfloat162*>(g_eh)[gi * 2 + 1] = h1;
}

// ---------------- kernel 1c: transpose x -> xh [token][d] bf16 ----------------
__global__ void vq_convx_kernel(const float* __restrict__ x) {
    __shared__ float t[64][33];
    int h0 = blockIdx.x * 32;
    int d0 = blockIdx.y * 64;
    int b  = blockIdx.z;
    int tx = threadIdx.x, ty = threadIdx.y;
    const float* xb = x + ((size_t)b * D_EMB + d0) * HW + h0;
    t[ty     ][tx] = xb[(size_t)ty * HW + tx];
    t[ty + 32][tx] = xb[(size_t)(ty + 32) * HW + tx];
    __syncthreads();
    float v0 = t[tx * 2][ty], v1 = t[tx * 2 + 1][ty];
    __nv_bfloat162 hp; hp.x = __float2bfloat16(v0); hp.y = __float2bfloat16(v1);
    size_t o = ((size_t)(b * HW + h0 + ty)) * D_EMB + d0;
    reinterpret_cast<__nv_bfloat162*>(g_xh + o)[tx] = hp;
}

// ---------------- kernel 2: HMMA screen (xh.eh) + approx top-candidates ------
// 128 CTAs x 256 threads (8 warps, warp tile 32m x 64n). A (xh, 128x256) resident
// in XOR-swizzled smem; codes streamed 128n x 64k per chunk, 4-stage cp.async
// pipeline. Epilogue tracks top-4 per slot (8 slots/token -> 32 candidates),
// final per-token trim to top-8 approx; exact fp32 rescore in vq_rescore8.
#define SMB_OFF  65536          // A = 64 KB
#define SMB_STG  16384          // B stage = 16 KB, 4 stages
#define SM_TOTAL2 131072

__global__ void __launch_bounds__(256, 1)
vq_argmin_mma_kernel()
{
    extern __shared__ char smem[];
    const uint32_t sbA = smem_u32(smem);
    const uint32_t sbB = sbA + SMB_OFF;
    const int tid  = threadIdx.x;
    const int lane = tid & 31;
    const int wid  = tid >> 5;
    const int wm   = wid >> 1;     // 0..3 -> m offset 32*wm
    const int wn   = wid & 1;      // 0..1 -> n offset 64*wn
    const int m0   = blockIdx.x << 7;

    // ---- resident A fill: [m][k] bf16, 512B rows, xor-swizzled ----
    {
        const uint4* gsrc = reinterpret_cast<const uint4*>(g_xh) + (size_t)m0 * 32;
        #pragma unroll
        for (int it = 0; it < 16; it++) {
            int i = tid + it * 256;
            int m = i >> 5;
            int s = i & 31;
            uint4 v = gsrc[m * 32 + s];
            uint32_t byte = (uint32_t)(m * 512 + s * 16);
            byte ^= (uint32_t)((m & 7) << 4);
            *reinterpret_cast<uint4*>(smem + byte) = v;
        }
    }

    // B-chunk fill via cp.async: chunk gc covers codes (gc>>2)*128.., k (gc&3)*64..
    auto issue_fill = [&](int gc) {
        const int k0t = (gc >> 2) << 7;
        const int c   = gc & 3;
        const uint32_t base = sbB + (gc & 3 ? 0 : 0);  // stage below
        const uint32_t stg  = sbB + (uint32_t)(gc & 3) * 0;  // placeholder
        (void)base; (void)stg;
        const uint32_t dstb = sbB + (uint32_t)((gc & 3) == (gc & 3) ? 0 : 0);
        (void)dstb;
        const uint32_t stage = sbB + (uint32_t)(((unsigned)gc) & 3u) * SMB_STG;
        #pragma unroll
        for (int it = 0; it < 4; it++) {
            int i = tid + it * 256;
            int n = i >> 3;
            int s = i & 7;
            uint32_t byte = (uint32_t)(n * 128 + s * 16);
            uint32_t dst  = stage + (byte ^ (uint32_t)((n & 7) << 4));
            const char* src = (const char*)g_eh
                + ((size_t)(k0t + n) * 256 + (size_t)c * 64 + (size_t)s * 8) * 2;
            CP_ASYNC16(dst, src);
        }
    };

    // prologue: 3 stages in flight
    issue_fill(0); CP_COMMIT();
    issue_fill(1); CP_COMMIT();
    issue_fill(2); CP_COMMIT();

    // lane-invariant ldmatrix addressing
    const int l7 = lane & 7, lt = lane >> 3;
    const int mlane = wm * 32 + ((lt & 1) << 3) + l7;   // + mf*16
    const int nlane = wn * 64 + ((lt & 1) << 3) + l7;   // + nq*16
    const int kloff = (lt >> 1) << 3;                   // 0 or 8
    const uint32_t aXor = (uint32_t)((mlane & 7) << 4);
    const uint32_t bXor = (uint32_t)((nlane & 7) << 4);

    float acc[2][8][4];
    #pragma unroll
    for (int a = 0; a < 2; a++)
        #pragma unroll
        for (int b = 0; b < 8; b++)
            #pragma unroll
            for (int c = 0; c < 4; c++) acc[a][b][c] = 0.0f;

    // top-4 per slot (slot = mf*2 + rowhalf), sorted ascending
    float v[4][4]; int id[4][4];
    #pragma unroll
    for (int s = 0; s < 4; s++)
        #pragma unroll
        for (int j = 0; j < 4; j++) { v[s][j] = 3.4e38f; id[s][j] = 0; }

    for (int t = 0; t < 64; ++t) {
        for (int c = 0; c < 4; ++c) {
            const int gc = (t << 2) + c;
            CP_WAIT_GROUP2();
            __syncthreads();
            if (gc + 3 < 256) issue_fill(gc + 3);
            CP_COMMIT();

            const uint32_t bBase = sbB + (uint32_t)(gc & 3) * SMB_STG;
            #pragma unroll
            for (int ks = 0; ks < 4; ks++) {
                const int kg = c * 64 + ks * 16;
                const int kk = ks * 16;
                const uint32_t akb = (uint32_t)((kg + kloff) * 2) ^ aXor;
                const uint32_t bkb = (uint32_t)((kk + kloff) * 2) ^ bXor;
                uint32_t af[2][4], bf[4][4];
                #pragma unroll
                for (int mf = 0; mf < 2; mf++)
                    ldsm4(af[mf], sbA + (uint32_t)((mlane + mf * 16) * 512) + akb);
                #pragma unroll
                for (int nq = 0; nq < 4; nq++)
                    ldsm4(bf[nq], bBase + (uint32_t)((nlane + nq * 16) * 128) + bkb);
                #pragma unroll
                for (int mf = 0; mf < 2; mf++)
                    #pragma unroll
                    for (int nq = 0; nq < 4; nq++) {
                        mma16816(acc[mf][2 * nq    ], af[mf], bf[nq][0], bf[nq][2]);
                        mma16816(acc[mf][2 * nq + 1], af[mf], bf[nq][1], bf[nq][3]);
                    }
            }
        }

        // ---- per-tile epilogue: dist = ||e||^2 - 2*dot, insert into top-4 ----
        const int nbase = (t << 7) + wn * 64 + (lane & 3) * 2;
        #pragma unroll
        for (int nf = 0; nf < 8; nf++) {
            const int n = nbase + nf * 8;
            float2 eq = *reinterpret_cast<const float2*>(g_esq + n);
            #pragma unroll
            for (int mf = 0; mf < 2; mf++) {
                float* a = acc[mf][nf];
                #pragma unroll
                for (int rh = 0; rh < 2; rh++) {
                    const int s = mf * 2 + rh;
                    float d0 = eq.x - 2.0f * a[2 * rh    ];
                    float d1 = eq.y - 2.0f * a[2 * rh + 1];
                    // insert d0 (index n)
                    if (d0 < v[s][3]) {
                        if (d0 < v[s][1]) {
                            if (d0 < v[s][0]) {
                                v[s][3]=v[s][2]; id[s][3]=id[s][2];
                                v[s][2]=v[s][1]; id[s][2]=id[s][1];
                                v[s][1]=v[s][0]; id[s][1]=id[s][0];
                                v[s][0]=d0; id[s][0]=n;
                            } else {
                                v[s][3]=v[s][2]; id[s][3]=id[s][2];
                                v[s][2]=v[s][1]; id[s][2]=id[s][1];
                                v[s][1]=d0; id[s][1]=n;
                            }
                        } else if (d0 < v[s][2]) {
                            v[s][3]=v[s][2]; id[s][3]=id[s][2];
                            v[s][2]=d0; id[s][2]=n;
                        } else { v[s][3]=d0; id[s][3]=n; }
                    }
                    // insert d1 (index n+1)
                    if (d1 < v[s][3]) {
                        if (d1 < v[s][1]) {
                            if (d1 < v[s][0]) {
                                v[s][3]=v[s][2]; id[s][3]=id[s][2];
                                v[s][2]=v[s][1]; id[s][2]=id[s][1];
                                v[s][1]=v[s][0]; id[s][1]=id[s][0];
                                v[s][0]=d1; id[s][0]=n+1;
                            } else {
                                v[s][3]=v[s][2]; id[s][3]=id[s][2];
                                v[s][2]=v[s][1]; id[s][2]=id[s][1];
                                v[s][1]=d1; id[s][1]=n+1;
                            }
                        } else if (d1 < v[s][2]) {
                            v[s][3]=v[s][2]; id[s][3]=id[s][2];
                            v[s][2]=d1; id[s][2]=n+1;
                        } else { v[s][3]=d1; id[s][3]=n+1; }
                    }
                    a[2*rh] = 0.0f; a[2*rh+1] = 0.0f;
                }
            }
        }
    }

    // ---- final: 32 candidates/token -> top-8 -> g_cand ----
    CP_WAIT_ALL();
    __syncthreads();
    float* sv = reinterpret_cast<float*>(smem);               // [128][33]
    int*   si = reinterpret_cast<int*>(smem + 17024);         // [128][33]
    const int contrib = wn * 4 + (lane & 3);                  // 0..7
    #pragma unroll
    for (int s = 0; s < 4; s++) {
        int m = wm * 32 + (s >> 1) * 16 + (s & 1) * 8 + (lane >> 2);
        #pragma unroll
        for (int j = 0; j < 4; j++) {
            sv[m * 33 + contrib * 4 + j] = v[s][j];
            si[m * 33 + contrib * 4 + j] = id[s][j];
        }
    }
    __syncthreads();
    if (tid < 128) {
        #pragma unroll
        for (int r = 0; r < 8; r++) {
            float bvv = 3.4e38f; int bii = 0x7fffffff; int bpos = 0;
            for (int s2 = 0; s2 < 32; s2++) {
                float vv = sv[tid * 33 + s2];
                int   ii = si[tid * 33 + s2];
                if (vv < bvv || (vv == bvv && ii < bii)) { bvv = vv; bii = ii; bpos = s2; }
            }
            g_cand[(m0 + tid) * 8 + r] = bii;
            sv[tid * 33 + bpos] = 3.4e38f;
        }
    }
}

// ---------------- kernel 2b: exact fp32 rescore of 8 candidates ----------------
// block (32,8): 32 consecutive tokens (same batch), ty = candidate slot.
__global__ void vq_rescore8_kernel(const float* __restrict__ x,
                                   const float* __restrict__ emb,
                                   float* __restrict__ idx_f_out)
{
    __shared__ float sx[32][257];
    __shared__ float rdv[8][32];
    __shared__ int   rdi[8][32];
    const int tx = threadIdx.x, ty = threadIdx.y;
    const int n0 = blockIdx.x * 32;
    const int b  = n0 >> 10;
    const int hw = (n0 & 1023) + tx;
    const int n  = n0 + tx;

    // cooperative load of x rows (coalesced in hw)
    for (int d = ty; d < D_EMB; d += 8)
        sx[tx][d] = x[(((size_t)(b * D_EMB + d)) << 10) + hw];
    __syncthreads();

    const int kc = g_cand[n * 8 + ty];
    const float4* ep = reinterpret_cast<const float4*>(emb + ((size_t)kc << 8));
    float s = 0.0f;
    #pragma unroll 8
    for (int j = 0; j < 64; j++) {
        float4 e4 = __ldg(ep + j);
        s += sx[tx][4*j  ] * e4.x + sx[tx][4*j+1] * e4.y
           + sx[tx][4*j+2] * e4.z + sx[tx][4*j+3] * e4.w;
    }
    rdv[ty][tx] = __ldg(&g_esq[kc]) - 2.0f * s;
    rdi[ty][tx] = kc;
    __syncthreads();
    if (ty == 0) {
        float best = rdv[0][tx]; int bidx = rdi[0][tx];
        #pragma unroll
        for (int j = 1; j < 8; j++) {
            float vv = rdv[j][tx]; int ii = rdi[j][tx];
            if (vv < best || (vv == best && ii < bidx)) { best = vv; bidx = ii; }
        }
        g_idx[n] = bidx;
        idx_f_out[n] = (float)bidx;
    }
}

// ---------------- kernel 3: gather q_st, loss, counts, dw ----------------
__global__ void vq_quant_kernel(const float* __restrict__ x,
                                const float* __restrict__ emb,
                                float* __restrict__ outq)
{
    const int tx = threadIdx.x, ty = threadIdx.y;
    const int hw = blockIdx.x * 32 + tx;
    const int b  = blockIdx.y;
    const int n  = (b << 10) + hw;
    const int code = g_idx[n];
    const float* erow = emb + ((size_t)code << 8);
    float lsum = 0.0f;
    const int d0 = ty * 32;
    #pragma unroll
    for (int j = 0; j < 8; j++) {
        const int d = d0 + j * 4;
        float4 e4 = __ldg(reinterpret_cast<const float4*>(erow + d));
        size_t xi = (((size_t)(b * D_EMB + d)) << 10) + hw;
        float xv0 = x[xi];
        float xv1 = x[xi + 1024];
        float xv2 = x[xi + 2048];
        float xv3 = x[xi + 3072];
        outq[xi       ] = e4.x;
        outq[xi + 1024] = e4.y;
        outq[xi + 2048] = e4.z;
        outq[xi + 3072] = e4.w;
        atomicAdd(&g_dw[(code << 8) + d    ], xv0);
        atomicAdd(&g_dw[(code << 8) + d + 1], xv1);
        atomicAdd(&g_dw[(code << 8) + d + 2], xv2);
        atomicAdd(&g_dw[(code << 8) + d + 3], xv3);
        float f0 = e4.x - xv0, f1 = e4.y - xv1, f2 = e4.z - xv2, f3 = e4.w - xv3;
        lsum += f0*f0 + f1*f1 + f2*f2 + f3*f3;
    }
    if (ty == 0) atomicAdd(&g_counts[code], 1.0f);

    __shared__ float s[256];
    int t = ty * 32 + tx;
    s[t] = lsum;
    __syncthreads();
    #pragma unroll
    for (int st = 128; st > 0; st >>= 1) {
        if (t < st) s[t] += s[t + st];
        __syncthreads();
    }
    if (t == 0) atomicAdd(&g_scal[0], s[0]);
}

// ---------------- kernel 4: EMA stage 1 ----------------
__global__ void vq_ema1_kernel(const float* __restrict__ ecs) {
    int k = blockIdx.x * 256 + threadIdx.x;
    float cnt = g_counts[k];
    float pre = ecs[k] * 0.99f + 0.01f * cnt;
    g_cs_pre[k] = pre;
    float p  = cnt * (1.0f / 16384.0f);
    float pl = p * logf(p + 1e-10f);

    __shared__ float sp[256], sl[256];
    int t = threadIdx.x;
    sp[t] = pre; sl[t] = pl;
    __syncthreads();
    #pragma unroll
    for (int st = 128; st > 0; st >>= 1) {
        if (t < st) { sp[t] += sp[t + st]; sl[t] += sl[t + st]; }
        __syncthreads();
    }
    if (t == 0) { atomicAdd(&g_scal[1], sp[0]); atomicAdd(&g_scal[2], sl[0]); }
}

// ---------------- kernel 5: EMA stage 2 ----------------
__global__ void vq_ema2_kernel(const float* __restrict__ emaw, float* __restrict__ out) {
    int k = blockIdx.x;
    int d = threadIdx.x;
    float ntot = g_scal[1];
    float ncs  = (g_cs_pre[k] + 1e-5f) / (ntot + 8192.0f * 1e-5f) * ntot;
    int i = (k << 8) + d;
    float nw = emaw[i] * 0.99f + 0.01f * g_dw[i];
    out[OFF_EMBO + i] = nw / ncs;
    out[OFF_EMAW + i] = nw;
    if (d == 0) out[OFF_CS + k] = ncs;
    if (k == 0 && d == 0) {
        out[OFF_LOSS] = 0.25f * g_scal[0] * (1.0f / 4194304.0f);
        out[OFF_PERP] = expf(-g_scal[2]);
    }
}

// ---------------- launch ----------------
extern "C" void kernel_launch(void* const* d_in, const int* in_sizes, int n_in,
                              void* d_out, int out_size)
{
    const float* x = nullptr; const float* emb = nullptr;
    const float* ecs = nullptr; const float* emaw = nullptr;
    for (int i = 0; i < n_in; i++) {
        int s = in_sizes[i];
        if (s == QST_N) x = (const float*)d_in[i];
        else if (s == K_EMB) ecs = (const float*)d_in[i];
        else if (s == K_EMB * D_EMB) {
            if (!emb) emb = (const float*)d_in[i];
            else emaw = (const float*)d_in[i];
        }
    }
    if (!x)    x    = (const float*)d_in[0];
    if (!emb)  emb  = (const float*)d_in[1];
    if (!ecs)  ecs  = (const float*)d_in[2];
    if (!emaw) emaw = (const float*)d_in[3];
    float* out = (float*)d_out;

    cudaFuncSetAttribute(vq_argmin_mma_kernel,
                         cudaFuncAttributeMaxDynamicSharedMemorySize, SM_TOTAL2);

    vq_zero_kernel<<<2048, 1024>>>();
    vq_convemb_kernel<<<2048, 256>>>(emb);
    vq_convx_kernel<<<dim3(32, 4, 16), dim3(32, 32)>>>(x);
    vq_esq_kernel<<<1024, 256>>>(emb);
    vq_argmin_mma_kernel<<<128, 256, SM_TOTAL2>>>();
    vq_rescore8_kernel<<<512, dim3(32, 8)>>>(x, emb, out + OFF_IDX);
    vq_quant_kernel<<<dim3(32, 16), dim3(32, 8)>>>(x, emb, out + OFF_QST);
    vq_ema1_kernel<<<32, 256>>>(ecs);
    vq_ema2_kernel<<<8192, 256>>>(emaw, out);
    (void)out_size;
}

// round 16
// speedup vs baseline: 2.9785x; 1.0627x over previous
#include <cuda_runtime.h>
#include <cuda_bf16.h>
#include <cstdint>
#include <math.h>

// ---------------- problem constants ----------------
#define K_EMB   8192
#define D_EMB   256
#define N_TOK   16384          // 16 * 32 * 32
#define HW      1024           // 32*32
#define BATCH   16
#define QST_N   4194304        // 16*256*32*32

// output layout (concatenated float32, reference tuple order)
#define OFF_LOSS  0LL
#define OFF_QST   1LL
#define OFF_PERP  4194305LL
#define OFF_EMBO  4194306LL
#define OFF_CS    6291458LL
#define OFF_EMAW  6299650LL
#define OFF_IDX   8396802LL

// ---------------- scratch (static device memory; no allocations) ----------------
__device__ float g_counts[K_EMB];
__device__ float g_dw[K_EMB * D_EMB];
__device__ float g_esq[K_EMB];
__device__ float g_cs_pre[K_EMB];
__device__ int   g_cand[N_TOK * 8];     // top-8 approx candidates per token
__device__ float g_scal[3];   // [0]=loss sum, [1]=ntot, [2]=sum p*log(p)

// fp8 (e4m3) screen buffers, uint4 for 16B alignment
__device__ uint4 g_x8[N_TOK * D_EMB / 16];   // [16384][256] token-major fp8
__device__ uint4 g_e8[K_EMB * D_EMB / 16];   // [8192][256] fp8

// ---------------- helpers ----------------
__device__ __forceinline__ uint32_t smem_u32(const void* p) {
    uint32_t a;
    asm("{ .reg .u64 t; cvta.to.shared.u64 t, %1; cvt.u32.u64 %0, t; }" : "=r"(a) : "l"(p));
    return a;
}
__device__ __forceinline__ void ldsm4(uint32_t r[4], uint32_t addr) {
    asm volatile("ldmatrix.sync.aligned.m8n8.x4.shared.b16 {%0,%1,%2,%3}, [%4];"
                 : "=r"(r[0]), "=r"(r[1]), "=r"(r[2]), "=r"(r[3]) : "r"(addr));
}
// fp8 e4m3 MMA: m16n8k32, fp32 accum
__device__ __forceinline__ void mma16832(float d[4], const uint32_t a[4],
                                         uint32_t b0, uint32_t b1) {
    asm volatile(
        "mma.sync.aligned.m16n8k32.row.col.f32.e4m3.e4m3.f32 "
        "{%0,%1,%2,%3}, {%4,%5,%6,%7}, {%8,%9}, {%0,%1,%2,%3};"
        : "+f"(d[0]), "+f"(d[1]), "+f"(d[2]), "+f"(d[3])
        : "r"(a[0]), "r"(a[1]), "r"(a[2]), "r"(a[3]), "r"(b0), "r"(b1));
}
// pack two floats -> e4m3x2 (lo -> low byte, hi -> high byte)
__device__ __forceinline__ unsigned short fp8x2(float lo, float hi) {
    unsigned short r;
    asm("cvt.rn.satfinite.e4m3x2.f32 %0, %1, %2;" : "=h"(r) : "f"(hi), "f"(lo));
    return r;
}
#define CP_ASYNC16(dst, src) \
    asm volatile("cp.async.cg.shared.global [%0], [%1], 16;" :: "r"(dst), "l"(src) : "memory")
#define CP_COMMIT()      asm volatile("cp.async.commit_group;" ::: "memory")
#define CP_WAIT_GROUP2() asm volatile("cp.async.wait_group 2;" ::: "memory")
#define CP_WAIT_ALL()    asm volatile("cp.async.wait_group 0;" ::: "memory")
#define REDV4(ptr, a, b, c, d) \
    asm volatile("red.global.add.v4.f32 [%0], {%1,%2,%3,%4};" \
        :: "l"(ptr), "f"(a), "f"(b), "f"(c), "f"(d) : "memory")

// ---------------- kernel 0: zero scratch ----------------
__global__ void vq_zero_kernel() {
    int gi = blockIdx.x * blockDim.x + threadIdx.x;   // covers 2097152
    g_dw[gi] = 0.0f;
    if (gi < K_EMB) g_counts[gi] = 0.0f;
    if (gi < 3)     g_scal[gi]   = 0.0f;
}

// ---------------- kernel 1: ||e_k||^2 ----------------
__global__ void vq_esq_kernel(const float* __restrict__ emb) {
    int gi   = blockIdx.x * blockDim.x + threadIdx.x;
    int k    = gi >> 5;
    int lane = gi & 31;
    const float4* p = reinterpret_cast<const float4*>(emb + (size_t)k * D_EMB + lane * 8);
    float4 a = p[0], b = p[1];
    float s = a.x*a.x + a.y*a.y + a.z*a.z + a.w*a.w
            + b.x*b.x + b.y*b.y + b.z*b.z + b.w*b.w;
    #pragma unroll
    for (int o = 16; o > 0; o >>= 1) s += __shfl_down_sync(0xffffffffu, s, o);
    if (lane == 0) g_esq[k] = s;
}

// ---------------- kernel 1b: emb -> fp8 ----------------
__global__ void vq_convemb_kernel(const float* __restrict__ emb) {
    int gi = blockIdx.x * 256 + threadIdx.x;          // 524288 threads x 4 elems
    float4 v = reinterpret_cast<const float4*>(emb)[gi];
    unsigned short p0 = fp8x2(v.x, v.y);
    unsigned short p1 = fp8x2(v.z, v.w);
    reinterpret_cast<uint32_t*>(g_e8)[gi] = (uint32_t)p0 | ((uint32_t)p1 << 16);
}

// ---------------- kernel 1c: transpose x -> fp8 [token][d] ----------------
__global__ void vq_convx_kernel(const float* __restrict__ x) {
    __shared__ float t[64][33];
    int h0 = blockIdx.x * 32;
    int d0 = blockIdx.y * 64;
    int b  = blockIdx.z;
    int tx = threadIdx.x, ty = threadIdx.y;
    const float* xb = x + ((size_t)b * D_EMB + d0) * HW + h0;
    t[ty     ][tx] = xb[(size_t)ty * HW + tx];
    t[ty + 32][tx] = xb[(size_t)(ty + 32) * HW + tx];
    __syncthreads();
    float v0 = t[tx * 2][ty], v1 = t[tx * 2 + 1][ty];
    size_t o = ((size_t)(b * HW + h0 + ty)) * D_EMB + d0;   // even
    reinterpret_cast<unsigned short*>(g_x8)[o / 2 + tx] = fp8x2(v0, v1);
}

// ---------------- kernel 2: FP8 MMA screen + approx top-candidates ----------
// 128 CTAs x 256 threads (8 warps, warp tile 32m x 64n). A (x fp8, 128x256B)
// resident in XOR-swizzled smem; codes streamed 128n x 64B-k per chunk
// (padded 128B rows), 4-stage cp.async pipeline. Epilogue tracks top-4 per
// slot (8 slots/token -> 32 candidates), trims to top-8 -> g_cand.
#define SMA_SZ   32768          // A = 128 rows x 256 B
#define SMB_STG  16384          // B stage: 128 rows x 128 B (64 real)
#define SM_TOTAL2 (SMA_SZ + 4 * SMB_STG)   // 98304

__global__ void __launch_bounds__(256, 1)
vq_argmin_mma_kernel()
{
    extern __shared__ char smem[];
    const uint32_t sbA = smem_u32(smem);
    const uint32_t sbB = sbA + SMA_SZ;
    const int tid  = threadIdx.x;
    const int lane = tid & 31;
    const int wid  = tid >> 5;
    const int wm   = wid >> 1;     // 0..3 -> m offset 32*wm
    const int wn   = wid & 1;      // 0..1 -> n offset 64*wn
    const int m0   = blockIdx.x << 7;

    // ---- resident A fill: [m][256B] fp8, xor-swizzled ----
    {
        const uint4* gsrc = g_x8 + (size_t)m0 * 16;
        #pragma unroll
        for (int it = 0; it < 8; it++) {
            int i = tid + it * 256;
            int m = i >> 4;
            int s = i & 15;
            uint4 v = gsrc[m * 16 + s];
            uint32_t byte = (uint32_t)(m * 256 + s * 16);
            byte ^= (uint32_t)((m & 7) << 4);
            *reinterpret_cast<uint4*>(smem + byte) = v;
        }
    }

    // B-chunk fill: chunk gc covers codes (gc>>2)*128.., k-bytes (gc&3)*64..
    auto issue_fill = [&](int gc) {
        const int k0t = (gc >> 2) << 7;
        const int c   = gc & 3;
        const uint32_t stage = sbB + (uint32_t)(((unsigned)gc) & 3u) * SMB_STG;
        #pragma unroll
        for (int it = 0; it < 2; it++) {
            int i = tid + it * 256;
            int n = i >> 2;
            int s = i & 3;
            uint32_t byte = (uint32_t)(n * 128 + s * 16);
            uint32_t dst  = stage + (byte ^ (uint32_t)((n & 7) << 4));
            const char* src = (const char*)g_e8
                + (size_t)(k0t + n) * 256 + (size_t)c * 64 + (size_t)s * 16;
            CP_ASYNC16(dst, src);
        }
    };

    issue_fill(0); CP_COMMIT();
    issue_fill(1); CP_COMMIT();
    issue_fill(2); CP_COMMIT();

    // lane-invariant ldmatrix addressing (byte granularity)
    const int l7 = lane & 7, lt = lane >> 3;
    const int mlane = wm * 32 + ((lt & 1) << 3) + l7;   // + mf*16
    const int nlane = wn * 64 + ((lt & 1) << 3) + l7;   // + nq*16
    const int kloff = (lt >> 1) << 4;                   // 0 or 16 bytes
    const uint32_t aXor = (uint32_t)((mlane & 7) << 4);
    const uint32_t bXor = (uint32_t)((nlane & 7) << 4);

    float acc[2][8][4];
    #pragma unroll
    for (int a = 0; a < 2; a++)
        #pragma unroll
        for (int b = 0; b < 8; b++)
            #pragma unroll
            for (int c = 0; c < 4; c++) acc[a][b][c] = 0.0f;

    // top-4 per slot (slot = mf*2 + rowhalf), sorted ascending
    float v[4][4]; int id[4][4];
    #pragma unroll
    for (int s = 0; s < 4; s++)
        #pragma unroll
        for (int j = 0; j < 4; j++) { v[s][j] = 3.4e38f; id[s][j] = 0; }

    for (int t = 0; t < 64; ++t) {
        for (int c = 0; c < 4; ++c) {
            const int gc = (t << 2) + c;
            CP_WAIT_GROUP2();
            __syncthreads();
            if (gc + 3 < 256) issue_fill(gc + 3);
            CP_COMMIT();

            const uint32_t bBase = sbB + (uint32_t)(gc & 3) * SMB_STG;
            #pragma unroll
            for (int ks = 0; ks < 2; ks++) {            // 32 k-bytes per mma
                const uint32_t akb = (uint32_t)(c * 64 + ks * 32 + kloff) ^ aXor;
                const uint32_t bkb = (uint32_t)(ks * 32 + kloff) ^ bXor;
                uint32_t af[2][4], bf[4][4];
                #pragma unroll
                for (int mf = 0; mf < 2; mf++)
                    ldsm4(af[mf], sbA + (uint32_t)((mlane + mf * 16) * 256) + akb);
                #pragma unroll
                for (int nq = 0; nq < 4; nq++)
                    ldsm4(bf[nq], bBase + (uint32_t)((nlane + nq * 16) * 128) + bkb);
                #pragma unroll
                for (int mf = 0; mf < 2; mf++)
                    #pragma unroll
                    for (int nq = 0; nq < 4; nq++) {
                        mma16832(acc[mf][2 * nq    ], af[mf], bf[nq][0], bf[nq][2]);
                        mma16832(acc[mf][2 * nq + 1], af[mf], bf[nq][1], bf[nq][3]);
                    }
            }
        }

        // ---- per-tile epilogue: dist = ||e||^2 - 2*dot, insert into top-4 ----
        const int nbase = (t << 7) + wn * 64 + (lane & 3) * 2;
        #pragma unroll
        for (int nf = 0; nf < 8; nf++) {
            const int n = nbase + nf * 8;
            float2 eq = *reinterpret_cast<const float2*>(g_esq + n);
            #pragma unroll
            for (int mf = 0; mf < 2; mf++) {
                float* a = acc[mf][nf];
                #pragma unroll
                for (int rh = 0; rh < 2; rh++) {
                    const int s = mf * 2 + rh;
                    float d0 = eq.x - 2.0f * a[2 * rh    ];
                    float d1 = eq.y - 2.0f * a[2 * rh + 1];
                    if (d0 < v[s][3]) {
                        if (d0 < v[s][1]) {
                            if (d0 < v[s][0]) {
                                v[s][3]=v[s][2]; id[s][3]=id[s][2];
                                v[s][2]=v[s][1]; id[s][2]=id[s][1];
                                v[s][1]=v[s][0]; id[s][1]=id[s][0];
                                v[s][0]=d0; id[s][0]=n;
                            } else {
                                v[s][3]=v[s][2]; id[s][3]=id[s][2];
                                v[s][2]=v[s][1]; id[s][2]=id[s][1];
                                v[s][1]=d0; id[s][1]=n;
                            }
                        } else if (d0 < v[s][2]) {
                            v[s][3]=v[s][2]; id[s][3]=id[s][2];
                            v[s][2]=d0; id[s][2]=n;
                        } else { v[s][3]=d0; id[s][3]=n; }
                    }
                    if (d1 < v[s][3]) {
                        if (d1 < v[s][1]) {
                            if (d1 < v[s][0]) {
                                v[s][3]=v[s][2]; id[s][3]=id[s][2];
                                v[s][2]=v[s][1]; id[s][2]=id[s][1];
                                v[s][1]=v[s][0]; id[s][1]=id[s][0];
                                v[s][0]=d1; id[s][0]=n+1;
                            } else {
                                v[s][3]=v[s][2]; id[s][3]=id[s][2];
                                v[s][2]=v[s][1]; id[s][2]=id[s][1];
                                v[s][1]=d1; id[s][1]=n+1;
                            }
                        } else if (d1 < v[s][2]) {
                            v[s][3]=v[s][2]; id[s][3]=id[s][2];
                            v[s][2]=d1; id[s][2]=n+1;
                        } else { v[s][3]=d1; id[s][3]=n+1; }
                    }
                    a[2*rh] = 0.0f; a[2*rh+1] = 0.0f;
                }
            }
        }
    }

    // ---- final: 32 candidates/token -> top-8 -> g_cand ----
    CP_WAIT_ALL();
    __syncthreads();
    float* sv = reinterpret_cast<float*>(smem);               // [128][33]
    int*   si = reinterpret_cast<int*>(smem + 17024);         // [128][33]
    const int contrib = wn * 4 + (lane & 3);                  // 0..7
    #pragma unroll
    for (int s = 0; s < 4; s++) {
        int m = wm * 32 + (s >> 1) * 16 + (s & 1) * 8 + (lane >> 2);
        #pragma unroll
        for (int j = 0; j < 4; j++) {
            sv[m * 33 + contrib * 4 + j] = v[s][j];
            si[m * 33 + contrib * 4 + j] = id[s][j];
        }
    }
    __syncthreads();
    if (tid < 128) {
        #pragma unroll
        for (int r = 0; r < 8; r++) {
            float bvv = 3.4e38f; int bii = 0x7fffffff; int bpos = 0;
            for (int s2 = 0; s2 < 32; s2++) {
                float vv = sv[tid * 33 + s2];
                int   ii = si[tid * 33 + s2];
                if (vv < bvv || (vv == bvv && ii < bii)) { bvv = vv; bii = ii; bpos = s2; }
            }
            g_cand[(m0 + tid) * 8 + r] = bii;
            sv[tid * 33 + bpos] = 3.4e38f;
        }
    }
}

// ---------------- kernel 2b: exact rescore + fused quant/loss/dw ------------
// block (32,8): tx = token within 32-chunk, ty = candidate slot / d-stripe.
__global__ void vq_rescore_quant_kernel(const float* __restrict__ x,
                                        const float* __restrict__ emb,
                                        float* __restrict__ outq,
                                        float* __restrict__ idx_f_out)
{
    __shared__ float sx[32][257];
    __shared__ float rdv[8][32];
    __shared__ int   rdi[8][32];
    __shared__ int   win[32];
    __shared__ float ls[256];
    const int tx = threadIdx.x, ty = threadIdx.y;
    const int n0 = blockIdx.x * 32;
    const int b  = n0 >> 10;
    const int hw = (n0 & 1023) + tx;
    const int n  = n0 + tx;

    // cooperative x load (coalesced in hw)
    for (int d = ty; d < D_EMB; d += 8)
        sx[tx][d] = x[(((size_t)(b * D_EMB + d)) << 10) + hw];
    __syncthreads();

    // exact fp32 distance for candidate ty
    {
        const int kc = g_cand[n * 8 + ty];
        const float4* ep = reinterpret_cast<const float4*>(emb + ((size_t)kc << 8));
        float s = 0.0f;
        #pragma unroll 8
        for (int j = 0; j < 64; j++) {
            float4 e4 = __ldg(ep + j);
            s += sx[tx][4*j  ] * e4.x + sx[tx][4*j+1] * e4.y
               + sx[tx][4*j+2] * e4.z + sx[tx][4*j+3] * e4.w;
        }
        rdv[ty][tx] = __ldg(&g_esq[kc]) - 2.0f * s;
        rdi[ty][tx] = kc;
    }
    __syncthreads();
    if (ty == 0) {
        float best = rdv[0][tx]; int bidx = rdi[0][tx];
        #pragma unroll
        for (int j = 1; j < 8; j++) {
            float vv = rdv[j][tx]; int ii = rdi[j][tx];
            if (vv < best || (vv == best && ii < bidx)) { best = vv; bidx = ii; }
        }
        win[tx] = bidx;
        idx_f_out[n] = (float)bidx;
        atomicAdd(&g_counts[bidx], 1.0f);
    }
    __syncthreads();

    // fused quant: q_st gather, loss, dw (vector red)
    const int code = win[tx];
    const float* erow = emb + ((size_t)code << 8);
    float lsum = 0.0f;
    const int d0 = ty * 32;
    #pragma unroll
    for (int j = 0; j < 8; j++) {
        const int d = d0 + j * 4;
        float4 e4 = __ldg(reinterpret_cast<const float4*>(erow + d));
        size_t xi = (((size_t)(b * D_EMB + d)) << 10) + hw;
        float xv0 = sx[tx][d], xv1 = sx[tx][d+1], xv2 = sx[tx][d+2], xv3 = sx[tx][d+3];
        outq[xi       ] = e4.x;
        outq[xi + 1024] = e4.y;
        outq[xi + 2048] = e4.z;
        outq[xi + 3072] = e4.w;
        REDV4(&g_dw[(code << 8) + d], xv0, xv1, xv2, xv3);
        float f0 = e4.x - xv0, f1 = e4.y - xv1, f2 = e4.z - xv2, f3 = e4.w - xv3;
        lsum += f0*f0 + f1*f1 + f2*f2 + f3*f3;
    }
    int t = ty * 32 + tx;
    ls[t] = lsum;
    __syncthreads();
    #pragma unroll
    for (int st = 128; st > 0; st >>= 1) {
        if (t < st) ls[t] += ls[t + st];
        __syncthreads();
    }
    if (t == 0) atomicAdd(&g_scal[0], ls[0]);
}

// ---------------- kernel 4: EMA stage 1 ----------------
__global__ void vq_ema1_kernel(const float* __restrict__ ecs) {
    int k = blockIdx.x * 256 + threadIdx.x;
    float cnt = g_counts[k];
    float pre = ecs[k] * 0.99f + 0.01f * cnt;
    g_cs_pre[k] = pre;
    float p  = cnt * (1.0f / 16384.0f);
    float pl = p * logf(p + 1e-10f);

    __shared__ float sp[256], sl[256];
    int t = threadIdx.x;
    sp[t] = pre; sl[t] = pl;
    __syncthreads();
    #pragma unroll
    for (int st = 128; st > 0; st >>= 1) {
        if (t < st) { sp[t] += sp[t + st]; sl[t] += sl[t + st]; }
        __syncthreads();
    }
    if (t == 0) { atomicAdd(&g_scal[1], sp[0]); atomicAdd(&g_scal[2], sl[0]); }
}

// ---------------- kernel 5: EMA stage 2 ----------------
__global__ void vq_ema2_kernel(const float* __restrict__ emaw, float* __restrict__ out) {
    int k = blockIdx.x;
    int d = threadIdx.x;
    float ntot = g_scal[1];
    float ncs  = (g_cs_pre[k] + 1e-5f) / (ntot + 8192.0f * 1e-5f) * ntot;
    int i = (k << 8) + d;
    float nw = emaw[i] * 0.99f + 0.01f * g_dw[i];
    out[OFF_EMBO + i] = nw / ncs;
    out[OFF_EMAW + i] = nw;
    if (d == 0) out[OFF_CS + k] = ncs;
    if (k == 0 && d == 0) {
        out[OFF_LOSS] = 0.25f * g_scal[0] * (1.0f / 4194304.0f);
        out[OFF_PERP] = expf(-g_scal[2]);
    }
}

// ---------------- launch ----------------
extern "C" void kernel_launch(void* const* d_in, const int* in_sizes, int n_in,
                              void* d_out, int out_size)
{
    const float* x = nullptr; const float* emb = nullptr;
    const float* ecs = nullptr; const float* emaw = nullptr;
    for (int i = 0; i < n_in; i++) {
        int s = in_sizes[i];
        if (s == QST_N) x = (const float*)d_in[i];
        else if (s == K_EMB) ecs = (const float*)d_in[i];
        else if (s == K_EMB * D_EMB) {
            if (!emb) emb = (const float*)d_in[i];
            else emaw = (const float*)d_in[i];
        }
    }
    if (!x)    x    = (const float*)d_in[0];
    if (!emb)  emb  = (const float*)d_in[1];
    if (!ecs)  ecs  = (const float*)d_in[2];
    if (!emaw) emaw = (const float*)d_in[3];
    float* out = (float*)d_out;

    cudaFuncSetAttribute(vq_argmin_mma_kernel,
                         cudaFuncAttributeMaxDynamicSharedMemorySize, SM_TOTAL2);

    vq_zero_kernel<<<2048, 1024>>>();
    vq_convemb_kernel<<<2048, 256>>>(emb);
    vq_convx_kernel<<<dim3(32, 4, 16), dim3(32, 32)>>>(x);
    vq_esq_kernel<<<1024, 256>>>(emb);
    vq_argmin_mma_kernel<<<128, 256, SM_TOTAL2>>>();
    vq_rescore_quant_kernel<<<512, dim3(32, 8)>>>(x, emb, out + OFF_QST, out + OFF_IDX);
    vq_ema1_kernel<<<32, 256>>>(ecs);
    vq_ema2_kernel<<<8192, 256>>>(emaw, out);
    (void)out_size;
}

// round 17
// speedup vs baseline: 3.2433x; 1.0889x over previous
#include <cuda_runtime.h>
#include <cuda_bf16.h>
#include <cstdint>
#include <math.h>

// ---------------- problem constants ----------------
#define K_EMB   8192
#define D_EMB   256
#define N_TOK   16384          // 16 * 32 * 32
#define HW      1024           // 32*32
#define BATCH   16
#define QST_N   4194304        // 16*256*32*32

// output layout (concatenated float32, reference tuple order)
#define OFF_LOSS  0LL
#define OFF_QST   1LL
#define OFF_PERP  4194305LL
#define OFF_EMBO  4194306LL
#define OFF_CS    6291458LL
#define OFF_EMAW  6299650LL
#define OFF_IDX   8396802LL

// ---------------- scratch (static device memory; no allocations) ----------------
__device__ float g_counts[K_EMB];
__device__ float g_dw[K_EMB * D_EMB];
__device__ float g_esq[K_EMB];
__device__ float g_cs_pre[K_EMB];
__device__ int   g_cand[N_TOK * 8];     // top-8 approx candidates per token
__device__ float g_scal[3];   // [0]=loss sum, [1]=ntot, [2]=sum p*log(p)

// fp8 (e4m3) codebook, uint4 for 16B alignment
__device__ uint4 g_e8[K_EMB * D_EMB / 16];   // [8192][256] fp8

// ---------------- helpers ----------------
__device__ __forceinline__ uint32_t smem_u32(const void* p) {
    uint32_t a;
    asm("{ .reg .u64 t; cvta.to.shared.u64 t, %1; cvt.u32.u64 %0, t; }" : "=r"(a) : "l"(p));
    return a;
}
__device__ __forceinline__ void ldsm4(uint32_t r[4], uint32_t addr) {
    asm volatile("ldmatrix.sync.aligned.m8n8.x4.shared.b16 {%0,%1,%2,%3}, [%4];"
                 : "=r"(r[0]), "=r"(r[1]), "=r"(r[2]), "=r"(r[3]) : "r"(addr));
}
// fp8 e4m3 MMA: m16n8k32, fp32 accum
__device__ __forceinline__ void mma16832(float d[4], const uint32_t a[4],
                                         uint32_t b0, uint32_t b1) {
    asm volatile(
        "mma.sync.aligned.m16n8k32.row.col.f32.e4m3.e4m3.f32 "
        "{%0,%1,%2,%3}, {%4,%5,%6,%7}, {%8,%9}, {%0,%1,%2,%3};"
        : "+f"(d[0]), "+f"(d[1]), "+f"(d[2]), "+f"(d[3])
        : "r"(a[0]), "r"(a[1]), "r"(a[2]), "r"(a[3]), "r"(b0), "r"(b1));
}
// pack two floats -> e4m3x2 (lo -> low byte, hi -> high byte)
__device__ __forceinline__ unsigned short fp8x2(float lo, float hi) {
    unsigned short r;
    asm("cvt.rn.satfinite.e4m3x2.f32 %0, %1, %2;" : "=h"(r) : "f"(hi), "f"(lo));
    return r;
}
#define CP_ASYNC16(dst, src) \
    asm volatile("cp.async.cg.shared.global [%0], [%1], 16;" :: "r"(dst), "l"(src) : "memory")
#define CP_COMMIT()      asm volatile("cp.async.commit_group;" ::: "memory")
#define CP_WAIT_GROUP2() asm volatile("cp.async.wait_group 2;" ::: "memory")
#define CP_WAIT_ALL()    asm volatile("cp.async.wait_group 0;" ::: "memory")
#define REDV4(ptr, a, b, c, d) \
    asm volatile("red.global.add.v4.f32 [%0], {%1,%2,%3,%4};" \
        :: "l"(ptr), "f"(a), "f"(b), "f"(c), "f"(d) : "memory")

// ---------------- kernel P: fused prep (emb->fp8, zero dw/counts/scal) -------
__global__ void vq_prep_kernel(const float* __restrict__ emb) {
    int gi = blockIdx.x * 256 + threadIdx.x;          // 524288 threads
    float4 v = reinterpret_cast<const float4*>(emb)[gi];
    unsigned short p0 = fp8x2(v.x, v.y);
    unsigned short p1 = fp8x2(v.z, v.w);
    reinterpret_cast<uint32_t*>(g_e8)[gi] = (uint32_t)p0 | ((uint32_t)p1 << 16);
    reinterpret_cast<float4*>(g_dw)[gi] = make_float4(0.f, 0.f, 0.f, 0.f);
    if (gi < K_EMB) g_counts[gi] = 0.0f;
    if (gi < 3)     g_scal[gi]   = 0.0f;
}

// ---------------- kernel 1: ||e_k||^2 ----------------
__global__ void vq_esq_kernel(const float* __restrict__ emb) {
    int gi   = blockIdx.x * blockDim.x + threadIdx.x;
    int k    = gi >> 5;
    int lane = gi & 31;
    const float4* p = reinterpret_cast<const float4*>(emb + (size_t)k * D_EMB + lane * 8);
    float4 a = p[0], b = p[1];
    float s = a.x*a.x + a.y*a.y + a.z*a.z + a.w*a.w
            + b.x*b.x + b.y*b.y + b.z*b.z + b.w*b.w;
    #pragma unroll
    for (int o = 16; o > 0; o >>= 1) s += __shfl_down_sync(0xffffffffu, s, o);
    if (lane == 0) g_esq[k] = s;
}

// ---------------- kernel 2: FP8 MMA screen + approx top-candidates ----------
// 128 CTAs x 256 threads (8 warps, warp tile 32m x 64n). A (x fp8, 128x256B)
// built IN-KERNEL from fp32 x via staged transpose, xor-swizzled smem.
// Codes streamed 128n x 128B-k per stage (fully used), 4-stage cp.async
// pipeline, 2 stages per 128n tile. Epilogue tracks top-4 per slot
// (8 slots/token -> 32 candidates), trims to top-8 -> g_cand.
#define SMA_SZ   32768          // A = 128 rows x 256 B
#define SMB_STG  16384          // B stage: 128 rows x 128 B
#define SM_TOTAL2 (SMA_SZ + 4 * SMB_STG)   // 98304

__global__ void __launch_bounds__(256, 1)
vq_argmin_mma_kernel(const float* __restrict__ x)
{
    extern __shared__ char smem[];
    const uint32_t sbA = smem_u32(smem);
    const uint32_t sbB = sbA + SMA_SZ;
    const int tid  = threadIdx.x;
    const int lane = tid & 31;
    const int wid  = tid >> 5;
    const int wm   = wid >> 1;     // 0..3 -> m offset 32*wm
    const int wn   = wid & 1;      // 0..1 -> n offset 64*wn
    const int m0   = blockIdx.x << 7;
    const int bb   = m0 >> 10;
    const int hw0  = m0 & 1023;

    // ---- build resident A from fp32 x: transpose + fp8, xor-swizzled ----
    {
        float* stag = reinterpret_cast<float*>(smem + SMA_SZ);   // [32][132]
        const float* xb = x + (size_t)bb * (D_EMB * HW) + hw0;
        const int r = tid >> 5;            // 0..7
        const int m = tid & 127;
        const int half = tid >> 7;         // 0/1
        for (int dd0 = 0; dd0 < 256; dd0 += 32) {
            #pragma unroll
            for (int q = 0; q < 4; q++) {
                int dd = r + q * 8;        // 0..31
                float4 v = *reinterpret_cast<const float4*>(
                    xb + (size_t)(dd0 + dd) * HW + lane * 4);
                float* sp = stag + dd * 132 + lane * 4;
                sp[0] = v.x; sp[1] = v.y; sp[2] = v.z; sp[3] = v.w;
            }
            __syncthreads();
            #pragma unroll
            for (int j = 0; j < 8; j++) {
                int d = half * 16 + 2 * j;                 // 0..31 within block
                float lo = stag[d * 132 + m];
                float hi = stag[(d + 1) * 132 + m];
                uint32_t byte = (uint32_t)(m * 256 + dd0 + d);
                byte ^= (uint32_t)((m & 7) << 4);
                *reinterpret_cast<unsigned short*>(smem + byte) = fp8x2(lo, hi);
            }
            __syncthreads();
        }
    }

    // B-stage fill: gh covers codes (gh>>1)*128.., k-bytes (gh&1)*128..
    auto issue_fill = [&](int gh) {
        const int k0t = (gh >> 1) << 7;
        const int kb0 = (gh & 1) << 7;
        const uint32_t stage = sbB + (uint32_t)(((unsigned)gh) & 3u) * SMB_STG;
        #pragma unroll
        for (int it = 0; it < 4; it++) {
            int i = tid + it * 256;
            int n = i >> 3;
            int s = i & 7;
            uint32_t byte = (uint32_t)(n * 128 + s * 16);
            uint32_t dst  = stage + (byte ^ (uint32_t)((n & 7) << 4));
            const char* src = (const char*)g_e8
                + (size_t)(k0t + n) * 256 + (size_t)kb0 + (size_t)s * 16;
            CP_ASYNC16(dst, src);
        }
    };

    issue_fill(0); CP_COMMIT();
    issue_fill(1); CP_COMMIT();
    issue_fill(2); CP_COMMIT();

    // lane-invariant ldmatrix addressing (byte granularity)
    const int l7 = lane & 7, lt = lane >> 3;
    const int mlane = wm * 32 + ((lt & 1) << 3) + l7;   // + mf*16
    const int nlane = wn * 64 + ((lt & 1) << 3) + l7;   // + nq*16
    const int kloff = (lt >> 1) << 4;                   // 0 or 16 bytes
    const uint32_t aXor = (uint32_t)((mlane & 7) << 4);
    const uint32_t bXor = (uint32_t)((nlane & 7) << 4);

    float acc[2][8][4];
    #pragma unroll
    for (int a = 0; a < 2; a++)
        #pragma unroll
        for (int b = 0; b < 8; b++)
            #pragma unroll
            for (int c = 0; c < 4; c++) acc[a][b][c] = 0.0f;

    // top-4 per slot (slot = mf*2 + rowhalf), sorted ascending
    float v[4][4]; int id[4][4];
    #pragma unroll
    for (int s = 0; s < 4; s++)
        #pragma unroll
        for (int j = 0; j < 4; j++) { v[s][j] = 3.4e38f; id[s][j] = 0; }

    for (int t = 0; t < 64; ++t) {
        #pragma unroll
        for (int half = 0; half < 2; ++half) {
            const int gh = (t << 1) + half;
            CP_WAIT_GROUP2();
            __syncthreads();
            if (gh + 3 < 128) issue_fill(gh + 3);
            CP_COMMIT();

            const uint32_t bBase = sbB + (uint32_t)(gh & 3) * SMB_STG;
            #pragma unroll
            for (int ks = 0; ks < 4; ks++) {            // 32 k-bytes per mma
                const uint32_t akb =
                    (uint32_t)(half * 128 + ks * 32 + kloff) ^ aXor;
                const uint32_t bkb = (uint32_t)(ks * 32 + kloff) ^ bXor;
                uint32_t af[2][4], bf[4][4];
                #pragma unroll
                for (int mf = 0; mf < 2; mf++)
                    ldsm4(af[mf], sbA + (uint32_t)((mlane + mf * 16) * 256) + akb);
                #pragma unroll
                for (int nq = 0; nq < 4; nq++)
                    ldsm4(bf[nq], bBase + (uint32_t)((nlane + nq * 16) * 128) + bkb);
                #pragma unroll
                for (int mf = 0; mf < 2; mf++)
                    #pragma unroll
                    for (int nq = 0; nq < 4; nq++) {
                        mma16832(acc[mf][2 * nq    ], af[mf], bf[nq][0], bf[nq][2]);
                        mma16832(acc[mf][2 * nq + 1], af[mf], bf[nq][1], bf[nq][3]);
                    }
            }
        }

        // ---- per-tile epilogue: dist = ||e||^2 - 2*dot, insert into top-4 ----
        const int nbase = (t << 7) + wn * 64 + (lane & 3) * 2;
        #pragma unroll
        for (int nf = 0; nf < 8; nf++) {
            const int n = nbase + nf * 8;
            float2 eq = *reinterpret_cast<const float2*>(g_esq + n);
            #pragma unroll
            for (int mf = 0; mf < 2; mf++) {
                float* a = acc[mf][nf];
                #pragma unroll
                for (int rh = 0; rh < 2; rh++) {
                    const int s = mf * 2 + rh;
                    float d0 = eq.x - 2.0f * a[2 * rh    ];
                    float d1 = eq.y - 2.0f * a[2 * rh + 1];
                    if (d0 < v[s][3]) {
                        if (d0 < v[s][1]) {
                            if (d0 < v[s][0]) {
                                v[s][3]=v[s][2]; id[s][3]=id[s][2];
                                v[s][2]=v[s][1]; id[s][2]=id[s][1];
                                v[s][1]=v[s][0]; id[s][1]=id[s][0];
                                v[s][0]=d0; id[s][0]=n;
                            } else {
                                v[s][3]=v[s][2]; id[s][3]=id[s][2];
                                v[s][2]=v[s][1]; id[s][2]=id[s][1];
                                v[s][1]=d0; id[s][1]=n;
                            }
                        } else if (d0 < v[s][2]) {
                            v[s][3]=v[s][2]; id[s][3]=id[s][2];
                            v[s][2]=d0; id[s][2]=n;
                        } else { v[s][3]=d0; id[s][3]=n; }
                    }
                    if (d1 < v[s][3]) {
                        if (d1 < v[s][1]) {
                            if (d1 < v[s][0]) {
                                v[s][3]=v[s][2]; id[s][3]=id[s][2];
                                v[s][2]=v[s][1]; id[s][2]=id[s][1];
                                v[s][1]=v[s][0]; id[s][1]=id[s][0];
                                v[s][0]=d1; id[s][0]=n+1;
                            } else {
                                v[s][3]=v[s][2]; id[s][3]=id[s][2];
                                v[s][2]=v[s][1]; id[s][2]=id[s][1];
                                v[s][1]=d1; id[s][1]=n+1;
                            }
                        } else if (d1 < v[s][2]) {
                            v[s][3]=v[s][2]; id[s][3]=id[s][2];
                            v[s][2]=d1; id[s][2]=n+1;
                        } else { v[s][3]=d1; id[s][3]=n+1; }
                    }
                    a[2*rh] = 0.0f; a[2*rh+1] = 0.0f;
                }
            }
        }
    }

    // ---- final: 32 candidates/token -> top-8 -> g_cand ----
    CP_WAIT_ALL();
    __syncthreads();
    float* sv = reinterpret_cast<float*>(smem);               // [128][33]
    int*   si = reinterpret_cast<int*>(smem + 17024);         // [128][33]
    const int contrib = wn * 4 + (lane & 3);                  // 0..7
    #pragma unroll
    for (int s = 0; s < 4; s++) {
        int m = wm * 32 + (s >> 1) * 16 + (s & 1) * 8 + (lane >> 2);
        #pragma unroll
        for (int j = 0; j < 4; j++) {
            sv[m * 33 + contrib * 4 + j] = v[s][j];
            si[m * 33 + contrib * 4 + j] = id[s][j];
        }
    }
    __syncthreads();
    if (tid < 128) {
        #pragma unroll
        for (int r = 0; r < 8; r++) {
            float bvv = 3.4e38f; int bii = 0x7fffffff; int bpos = 0;
            for (int s2 = 0; s2 < 32; s2++) {
                float vv = sv[tid * 33 + s2];
                int   ii = si[tid * 33 + s2];
                if (vv < bvv || (vv == bvv && ii < bii)) { bvv = vv; bii = ii; bpos = s2; }
            }
            g_cand[(m0 + tid) * 8 + r] = bii;
            sv[tid * 33 + bpos] = 3.4e38f;
        }
    }
}

// ---------------- kernel 2b: exact rescore + fused quant/loss/dw ------------
// block (32,8) = 256 thr, grid 512 (32 tokens each).
// Phase B: warp-per-(token,cand) with lanes striding d -> coalesced emb reads.
__global__ void vq_rescore_quant_kernel(const float* __restrict__ x,
                                        const float* __restrict__ emb,
                                        float* __restrict__ outq,
                                        float* __restrict__ idx_f_out)
{
    __shared__ float sx[32][257];
    __shared__ float rdv[8][32];
    __shared__ int   rdi[8][32];
    __shared__ int   win[32];
    __shared__ float ls[256];
    const int tx = threadIdx.x, ty = threadIdx.y;
    const int tid = ty * 32 + tx;
    const int lane = tx;                  // within warp ty
    const int n0 = blockIdx.x * 32;
    const int b  = n0 >> 10;
    const int hw = (n0 & 1023) + tx;

    // phase A: cooperative x load (coalesced in hw)
    for (int d = ty; d < D_EMB; d += 8)
        sx[tx][d] = x[(((size_t)(b * D_EMB + d)) << 10) + hw];
    __syncthreads();

    // phase B: 256 (token,cand) tasks, 32 per warp; lanes stride d
    #pragma unroll 4
    for (int i = 0; i < 32; i++) {
        const int task = ty * 32 + i;
        const int tk = task >> 3;        // token 0..31
        const int c  = task & 7;         // candidate 0..7
        const int kc = g_cand[(n0 + tk) * 8 + c];
        const float* er = emb + ((size_t)kc << 8);
        float s = 0.0f;
        #pragma unroll
        for (int j = 0; j < 8; j++) {
            int d = lane + 32 * j;
            s += __ldg(er + d) * sx[tk][d];
        }
        #pragma unroll
        for (int o = 16; o > 0; o >>= 1) s += __shfl_down_sync(0xffffffffu, s, o);
        if (lane == 0) {
            rdv[c][tk] = __ldg(&g_esq[kc]) - 2.0f * s;
            rdi[c][tk] = kc;
        }
    }
    __syncthreads();
    if (tid < 32) {
        float best = rdv[0][tid]; int bidx = rdi[0][tid];
        #pragma unroll
        for (int j = 1; j < 8; j++) {
            float vv = rdv[j][tid]; int ii = rdi[j][tid];
            if (vv < best || (vv == best && ii < bidx)) { best = vv; bidx = ii; }
        }
        win[tid] = bidx;
        idx_f_out[n0 + tid] = (float)bidx;
        atomicAdd(&g_counts[bidx], 1.0f);
    }
    __syncthreads();

    // phase C: fused quant (q_st gather, loss, dw via red.v4)
    const int code = win[tx];
    const float* erow = emb + ((size_t)code << 8);
    float lsum = 0.0f;
    const int d0 = ty * 32;
    #pragma unroll
    for (int j = 0; j < 8; j++) {
        const int d = d0 + j * 4;
        float4 e4 = __ldg(reinterpret_cast<const float4*>(erow + d));
        size_t xi = (((size_t)(b * D_EMB + d)) << 10) + hw;
        float xv0 = sx[tx][d], xv1 = sx[tx][d+1], xv2 = sx[tx][d+2], xv3 = sx[tx][d+3];
        outq[xi       ] = e4.x;
        outq[xi + 1024] = e4.y;
        outq[xi + 2048] = e4.z;
        outq[xi + 3072] = e4.w;
        REDV4(&g_dw[(code << 8) + d], xv0, xv1, xv2, xv3);
        float f0 = e4.x - xv0, f1 = e4.y - xv1, f2 = e4.z - xv2, f3 = e4.w - xv3;
        lsum += f0*f0 + f1*f1 + f2*f2 + f3*f3;
    }
    ls[tid] = lsum;
    __syncthreads();
    #pragma unroll
    for (int st = 128; st > 0; st >>= 1) {
        if (tid < st) ls[tid] += ls[tid + st];
        __syncthreads();
    }
    if (tid == 0) atomicAdd(&g_scal[0], ls[0]);
}

// ---------------- kernel 4: EMA stage 1 ----------------
__global__ void vq_ema1_kernel(const float* __restrict__ ecs) {
    int k = blockIdx.x * 256 + threadIdx.x;
    float cnt = g_counts[k];
    float pre = ecs[k] * 0.99f + 0.01f * cnt;
    g_cs_pre[k] = pre;
    float p  = cnt * (1.0f / 16384.0f);
    float pl = p * logf(p + 1e-10f);

    __shared__ float sp[256], sl[256];
    int t = threadIdx.x;
    sp[t] = pre; sl[t] = pl;
    __syncthreads();
    #pragma unroll
    for (int st = 128; st > 0; st >>= 1) {
        if (t < st) { sp[t] += sp[t + st]; sl[t] += sl[t + st]; }
        __syncthreads();
    }
    if (t == 0) { atomicAdd(&g_scal[1], sp[0]); atomicAdd(&g_scal[2], sl[0]); }
}

// ---------------- kernel 5: EMA stage 2 (vectorized) ----------------
__global__ void vq_ema2_kernel(const float* __restrict__ emaw, float* __restrict__ out) {
    int i4 = blockIdx.x * 256 + threadIdx.x;    // 524288 float4 slots
    int k  = i4 >> 6;
    float ntot = g_scal[1];
    float ncs  = (g_cs_pre[k] + 1e-5f) / (ntot + 8192.0f * 1e-5f) * ntot;
    float inv  = 1.0f / ncs;
    float4 w  = reinterpret_cast<const float4*>(emaw)[i4];
    float4 dw = reinterpret_cast<const float4*>(g_dw)[i4];
    float n0 = w.x * 0.99f + 0.01f * dw.x;
    float n1 = w.y * 0.99f + 0.01f * dw.y;
    float n2 = w.z * 0.99f + 0.01f * dw.z;
    float n3 = w.w * 0.99f + 0.01f * dw.w;
    long long i = (long long)i4 * 4;
    out[OFF_EMAW + i    ] = n0;
    out[OFF_EMAW + i + 1] = n1;
    out[OFF_EMAW + i + 2] = n2;
    out[OFF_EMAW + i + 3] = n3;
    out[OFF_EMBO + i    ] = n0 * inv;
    out[OFF_EMBO + i + 1] = n1 * inv;
    out[OFF_EMBO + i + 2] = n2 * inv;
    out[OFF_EMBO + i + 3] = n3 * inv;
    if ((i4 & 63) == 0) out[OFF_CS + k] = ncs;
    if (i4 == 0) {
        out[OFF_LOSS] = 0.25f * g_scal[0] * (1.0f / 4194304.0f);
        out[OFF_PERP] = expf(-g_scal[2]);
    }
}

// ---------------- launch ----------------
extern "C" void kernel_launch(void* const* d_in, const int* in_sizes, int n_in,
                              void* d_out, int out_size)
{
    const float* x = nullptr; const float* emb = nullptr;
    const float* ecs = nullptr; const float* emaw = nullptr;
    for (int i = 0; i < n_in; i++) {
        int s = in_sizes[i];
        if (s == QST_N) x = (const float*)d_in[i];
        else if (s == K_EMB) ecs = (const float*)d_in[i];
        else if (s == K_EMB * D_EMB) {
            if (!emb) emb = (const float*)d_in[i];
            else emaw = (const float*)d_in[i];
        }
    }
    if (!x)    x    = (const float*)d_in[0];
    if (!emb)  emb  = (const float*)d_in[1];
    if (!ecs)  ecs  = (const float*)d_in[2];
    if (!emaw) emaw = (const float*)d_in[3];
    float* out = (float*)d_out;

    cudaFuncSetAttribute(vq_argmin_mma_kernel,
                         cudaFuncAttributeMaxDynamicSharedMemorySize, SM_TOTAL2);

    vq_prep_kernel<<<2048, 256>>>(emb);
    vq_esq_kernel<<<1024, 256>>>(emb);
    vq_argmin_mma_kernel<<<128, 256, SM_TOTAL2>>>(x);
    vq_rescore_quant_kernel<<<512, dim3(32, 8)>>>(x, emb, out + OFF_QST, out + OFF_IDX);
    vq_ema1_kernel<<<32, 256>>>(ecs);
    vq_ema2_kernel<<<2048, 256>>>(emaw, out);
    (void)out_size;
}